// round 7
// baseline (speedup 1.0000x reference)
#include <cuda_runtime.h>
#include <cuda_bf16.h>
#include <cstdint>

// ---------------------------------------------------------------------------
// FeedBack LSTM via mma.sync bf16 (baseline PTX; sm_103 target, no 'a' feats).
// z = h@Wh (bf16 hi/lo split, 3 MMA terms, fp32 accum) + x@Wx + b, fused
// LSTM cell update in registers (gate-interleaved N permutation).
// R7: R6 + pipeline drain fix (wait_group 0 on the last chunk — R6 raced).
// B=16384, T=48, F=4, UNITS=256 (z width 1024), OUT_STEPS=24.
// ---------------------------------------------------------------------------

namespace {
constexpr int BATCH = 16384;
constexpr int SEQ_T = 48;
constexpr int FDIM  = 4;
constexpr int NU    = 256;
constexpr int NOUT  = 24;
constexpr int Z4    = 1024;

constexpr int THREADS = 512;        // 16 warps: 4 m-warps x 4 n-warps
constexpr int ROWB = 80;            // padded tile row: 64B data + 16B pad
constexpr int TILE_B = 128 * ROWB;  // 10240 bytes per 128x32 tile
constexpr int TILE_E = TILE_B / 2;  // 5120 bf16 elems
constexpr int STAGE_B = 4 * TILE_B; // AH|AL|BH|BL = 40960
constexpr int NSTAGE = 3;
constexpr int SMEM_WX = NSTAGE * STAGE_B;       // 122880
constexpr int SMEM_BIAS = SMEM_WX + 4*128*4;    // 124928
constexpr int SMEM_TOTAL = SMEM_BIAS + 512 + 64; // 125504
}

// ---------------- device state (allocation-free) ----------------
// A = h as bf16 hi/lo, double-buffered, padded chunk layout:
// [buf][rt(128)][kc(8)] tiles of 128 rows x 80B (32 k elems + pad).
__device__ __align__(16) __nv_bfloat16 g_ah[2 * 128 * 8 * TILE_E];
__device__ __align__(16) __nv_bfloat16 g_al[2 * 128 * 8 * TILE_E];
// B = Wh permuted (gate-interleaved), padded chunk layout: [nt(8)][kc(8)].
__device__ __align__(16) __nv_bfloat16 g_bh[8 * 8 * TILE_E];
__device__ __align__(16) __nv_bfloat16 g_bl[8 * 8 * TILE_E];
// permuted Wx / b (fp32)
__device__ float g_wxp[FDIM * Z4];
__device__ float g_bp[Z4];
// fp32 state
__device__ float g_h[BATCH * NU];
__device__ float g_c[BATCH * NU];
__device__ __align__(16) float g_pred[BATCH * FDIM];

// ---------------- ptx helpers (baseline PTX only) ----------------
__device__ __forceinline__ void cp16(uint32_t dst, const void* src) {
    asm volatile("cp.async.cg.shared.global [%0], [%1], 16;"
                 :: "r"(dst), "l"(__cvta_generic_to_global(src)) : "memory");
}
__device__ __forceinline__ void ldsm4(uint32_t* r, uint32_t a) {
    asm volatile("ldmatrix.sync.aligned.m8n8.x4.shared.b16 {%0,%1,%2,%3}, [%4];"
                 : "=r"(r[0]), "=r"(r[1]), "=r"(r[2]), "=r"(r[3]) : "r"(a));
}
__device__ __forceinline__ void ldsm2(uint32_t* r, uint32_t a) {
    asm volatile("ldmatrix.sync.aligned.m8n8.x2.shared.b16 {%0,%1}, [%2];"
                 : "=r"(r[0]), "=r"(r[1]) : "r"(a));
}
__device__ __forceinline__ void mma16816(float* d, const uint32_t* a,
                                         const uint32_t* b) {
    asm volatile(
        "mma.sync.aligned.m16n8k16.row.col.f32.bf16.bf16.f32 "
        "{%0,%1,%2,%3}, {%4,%5,%6,%7}, {%8,%9}, {%0,%1,%2,%3};"
        : "+f"(d[0]), "+f"(d[1]), "+f"(d[2]), "+f"(d[3])
        : "r"(a[0]), "r"(a[1]), "r"(a[2]), "r"(a[3]), "r"(b[0]), "r"(b[1]));
}
__device__ __forceinline__ float sigmoid_acc(float x) {
    return 0.5f * (1.0f + tanhf(0.5f * x));
}

// ---------------- prep kernels ----------------
// Permutation: permuted col p -> nt=p>>7, loc=p&127; wn=loc>>5, g=(loc>>3)&3,
// ul=loc&7; unit u = nt*32 + wn*8 + ul; original col oc = g*256 + u.
__global__ void prep_weights(const float* __restrict__ Wh) {
    int idx = blockIdx.x * 256 + threadIdx.x;   // 262144 = 1024 p x 256 k
    int p = idx >> 8;
    int k = idx & 255;
    int nt = p >> 7, loc = p & 127;
    int wn = loc >> 5, g = (loc >> 3) & 3, ul = loc & 7;
    int u = nt * 32 + wn * 8 + ul;
    int oc = g * 256 + u;
    float v = Wh[k * Z4 + oc];
    __nv_bfloat16 hi = __float2bfloat16(v);
    __nv_bfloat16 lo = __float2bfloat16(v - __bfloat162float(hi));
    int kc = k >> 5, kk = k & 31;
    int e = (nt * 8 + kc) * TILE_E + loc * (ROWB / 2) + kk;
    g_bh[e] = hi;
    g_bl[e] = lo;
}

__global__ void prep_wxb(const float* __restrict__ Wx, const float* __restrict__ b) {
    int p = threadIdx.x;                        // 0..1023
    int nt = p >> 7, loc = p & 127;
    int wn = loc >> 5, g = (loc >> 3) & 3, ul = loc & 7;
    int oc = g * 256 + (nt * 32 + wn * 8 + ul);
    g_bp[p] = b[oc];
    #pragma unroll
    for (int f = 0; f < FDIM; f++)
        g_wxp[f * Z4 + p] = Wx[f * Z4 + oc];
}

// ---------------- main timestep kernel ----------------
__global__ void __launch_bounds__(THREADS, 1)
lstm_step_mma(const float* __restrict__ xt, int xstride,
              const __nv_bfloat16* __restrict__ a_in_h,
              const __nv_bfloat16* __restrict__ a_in_l,
              __nv_bfloat16* __restrict__ a_out_h,
              __nv_bfloat16* __restrict__ a_out_l,
              int first)
{
    extern __shared__ char smem[];
    const uint32_t sb = (uint32_t)__cvta_generic_to_shared(smem);
    const int tid  = threadIdx.x;
    const int lane = tid & 31;
    const int wid  = tid >> 5;
    const int wm   = wid & 3;        // m-warp (rows wm*32..+32)
    const int wn   = wid >> 2;       // n-warp (cols wn*32..+32)
    const int nt = blockIdx.x;       // unit tile (0..7): units nt*32..+32
    const int rt = blockIdx.y;       // row tile (0..127)
    const int rbase = rt * 128;

    // permuted Wx / bias slices for this nt
    float* wx_s = (float*)(smem + SMEM_WX);     // [4][128]
    float* bp_s = (float*)(smem + SMEM_BIAS);   // [128]
    for (int i = tid; i < 4 * 128; i += THREADS) {
        int f = i >> 7, j = i & 127;
        wx_s[i] = g_wxp[f * Z4 + nt * 128 + j];
    }
    if (tid < 128) bp_s[tid] = g_bp[nt * 128 + tid];
    __syncthreads();

    // accumulators: d[mi][gate][frag]
    float d[2][4][4];
    #pragma unroll
    for (int mi = 0; mi < 2; mi++)
        #pragma unroll
        for (int g = 0; g < 4; g++)
            #pragma unroll
            for (int r = 0; r < 4; r++)
                d[mi][g][r] = 0.0f;

    if (!first) {
        auto issue = [&](int c) {
            const uint32_t st = sb + (uint32_t)((c % NSTAGE) * STAGE_B);
            const __nv_bfloat16* srcs[4] = {
                a_in_h + (rt * 8 + c) * TILE_E,
                a_in_l + (rt * 8 + c) * TILE_E,
                g_bh   + (nt * 8 + c) * TILE_E,
                g_bl   + (nt * 8 + c) * TILE_E };
            #pragma unroll
            for (int t4 = 0; t4 < 4; t4++) {
                const char* s = (const char*)srcs[t4];
                for (int i = tid; i < TILE_B / 16; i += THREADS)
                    cp16(st + t4 * TILE_B + i * 16, s + i * 16);
            }
            asm volatile("cp.async.commit_group;" ::: "memory");
        };

        issue(0);
        issue(1);

        for (int c = 0; c < 8; c++) {
            // Drain: last chunk must wait for ALL outstanding copies (its own
            // group is the most recent one; wait_group 1 would race it).
            if (c < 7)
                asm volatile("cp.async.wait_group 1;" ::: "memory");
            else
                asm volatile("cp.async.wait_group 0;" ::: "memory");
            __syncthreads();

            const uint32_t st = sb + (uint32_t)((c % NSTAGE) * STAGE_B);
            #pragma unroll
            for (int k16 = 0; k16 < 2; k16++) {
                // A fragments (hi/lo), 2 m-subtiles of 16 rows
                uint32_t ah[2][4], al[2][4];
                const int arow = wm * 32 + (lane & 15);
                const int akb  = k16 * 32 + ((lane & 16) ? 16 : 0);
                #pragma unroll
                for (int mi = 0; mi < 2; mi++) {
                    uint32_t ad = st + (uint32_t)((arow + mi * 16) * ROWB + akb);
                    ldsm4(ah[mi], ad);
                    ldsm4(al[mi], ad + TILE_B);
                }
                // B fragments (hi/lo), 4 gate-subtiles of 8 cols
                uint32_t bh[4][2], bl[4][2];
                const int bln = lane & 7;
                const int bkb = k16 * 32 + ((lane & 8) ? 16 : 0);
                #pragma unroll
                for (int g = 0; g < 4; g++) {
                    uint32_t ad = st + (uint32_t)(2 * TILE_B +
                        (wn * 32 + g * 8 + bln) * ROWB + bkb);
                    ldsm2(bh[g], ad);
                    ldsm2(bl[g], ad + TILE_B);
                }
                // 3-term MMAs
                #pragma unroll
                for (int mi = 0; mi < 2; mi++)
                    #pragma unroll
                    for (int g = 0; g < 4; g++) {
                        mma16816(d[mi][g], ah[mi], bh[g]);
                        mma16816(d[mi][g], al[mi], bh[g]);
                        mma16816(d[mi][g], ah[mi], bl[g]);
                    }
            }
            if (c + 2 < 8) issue(c + 2);
        }
    }

    // ---- epilogue: z -> gates -> c,h; write fp32 h + bf16 hi/lo A tiles ----
    const int q  = lane >> 2;       // row within m8
    const int s4 = lane & 3;        // col pair within n8
    #pragma unroll
    for (int mi = 0; mi < 2; mi++) {
        #pragma unroll
        for (int rh = 0; rh < 2; rh++) {
            const int row = rbase + wm * 32 + mi * 16 + q + rh * 8;
            const float4 xv = *reinterpret_cast<const float4*>(
                &xt[(long)row * xstride]);
            float hn2[2];
            #pragma unroll
            for (int par = 0; par < 2; par++) {
                const int ul = s4 * 2 + par;                  // 0..7
                const int u = nt * 32 + wn * 8 + ul;
                const int ci = row * NU + u;
                const float cold = first ? 0.0f : g_c[ci];
                float z[4];
                #pragma unroll
                for (int g = 0; g < 4; g++) {
                    const int nl = wn * 32 + g * 8 + ul;      // permuted col
                    float zz = bp_s[nl] + d[mi][g][rh * 2 + par];
                    zz = fmaf(xv.x, wx_s[nl],       zz);
                    zz = fmaf(xv.y, wx_s[128 + nl], zz);
                    zz = fmaf(xv.z, wx_s[256 + nl], zz);
                    zz = fmaf(xv.w, wx_s[384 + nl], zz);
                    z[g] = zz;
                }
                const float ig = sigmoid_acc(z[0]);
                const float fg = sigmoid_acc(z[1]);
                const float gg = tanhf(z[2]);
                const float og = sigmoid_acc(z[3]);
                const float cn = fg * cold + ig * gg;
                const float hn = og * tanhf(cn);
                g_c[ci] = cn;
                g_h[ci] = hn;
                hn2[par] = hn;
            }
            // pack bf16 hi/lo pair, store into next-step A layout
            const int kk = wn * 8 + s4 * 2;                   // k within chunk nt
            const long eb = (long)(rt * 8 + nt) * TILE_E +
                            (row & 127) * (ROWB / 2) + kk;
            __nv_bfloat16 h0 = __float2bfloat16(hn2[0]);
            __nv_bfloat16 h1 = __float2bfloat16(hn2[1]);
            __nv_bfloat16 l0 = __float2bfloat16(hn2[0] - __bfloat162float(h0));
            __nv_bfloat16 l1 = __float2bfloat16(hn2[1] - __bfloat162float(h1));
            uint32_t ph = (uint32_t)__bfloat16_as_ushort(h0) |
                          ((uint32_t)__bfloat16_as_ushort(h1) << 16);
            uint32_t pl = (uint32_t)__bfloat16_as_ushort(l0) |
                          ((uint32_t)__bfloat16_as_ushort(l1) << 16);
            *reinterpret_cast<uint32_t*>(&a_out_h[eb]) = ph;
            *reinterpret_cast<uint32_t*>(&a_out_l[eb]) = pl;
        }
    }
}

// pred = h @ Wd + bd ; writes output slice and feedback buffer.
__global__ void pred_kernel(const float* __restrict__ h,
                            const float* __restrict__ Wd,
                            const float* __restrict__ bd,
                            float* __restrict__ out, int ostride,
                            float* __restrict__ pred)
{
    const int gwarp = (blockIdx.x * blockDim.x + threadIdx.x) >> 5;
    const int lane  = threadIdx.x & 31;
    if (gwarp >= BATCH) return;

    const float* hrow = h + gwarp * NU;
    float a0 = 0.f, a1 = 0.f, a2 = 0.f, a3 = 0.f;
    #pragma unroll
    for (int k = lane; k < NU; k += 32) {
        float hv = hrow[k];
        float4 wv = *reinterpret_cast<const float4*>(&Wd[k * 4]);
        a0 = fmaf(hv, wv.x, a0);
        a1 = fmaf(hv, wv.y, a1);
        a2 = fmaf(hv, wv.z, a2);
        a3 = fmaf(hv, wv.w, a3);
    }
    #pragma unroll
    for (int off = 16; off > 0; off >>= 1) {
        a0 += __shfl_down_sync(0xffffffffu, a0, off);
        a1 += __shfl_down_sync(0xffffffffu, a1, off);
        a2 += __shfl_down_sync(0xffffffffu, a2, off);
        a3 += __shfl_down_sync(0xffffffffu, a3, off);
    }
    if (lane == 0) {
        float4 r = make_float4(a0 + bd[0], a1 + bd[1], a2 + bd[2], a3 + bd[3]);
        *reinterpret_cast<float4*>(&out[(long)gwarp * ostride]) = r;
        *reinterpret_cast<float4*>(&pred[gwarp * 4]) = r;
    }
}

extern "C" void kernel_launch(void* const* d_in, const int* in_sizes, int n_in,
                              void* d_out, int out_size)
{
    const float* x  = (const float*)d_in[0];
    const float* Wx = (const float*)d_in[1];
    const float* Wh = (const float*)d_in[2];
    const float* b  = (const float*)d_in[3];
    const float* Wd = (const float*)d_in[4];
    const float* bd = (const float*)d_in[5];
    float* out = (float*)d_out;

    cudaFuncSetAttribute(lstm_step_mma,
                         cudaFuncAttributeMaxDynamicSharedMemorySize, SMEM_TOTAL);

    float* pred_ptr = nullptr;
    float* h_ptr = nullptr;
    __nv_bfloat16* ah = nullptr;
    __nv_bfloat16* al = nullptr;
    cudaGetSymbolAddress((void**)&pred_ptr, g_pred);
    cudaGetSymbolAddress((void**)&h_ptr, g_h);
    cudaGetSymbolAddress((void**)&ah, g_ah);
    cudaGetSymbolAddress((void**)&al, g_al);
    const long BUFE = 128L * 8 * TILE_E;
    __nv_bfloat16* ahb[2] = {ah, ah + BUFE};
    __nv_bfloat16* alb[2] = {al, al + BUFE};

    // weight prep (re-run every replay -> deterministic)
    prep_weights<<<1024, 256>>>(Wh);
    prep_wxb<<<1, 1024>>>(Wx, b);

    const dim3 sgrid(8, 128);                 // (unit tiles, row tiles)
    const int pblocks = (BATCH * 32) / 256;

    int step = 0;
    // step 0: h=c=0 -> GEMM skipped, epilogue seeds state
    lstm_step_mma<<<sgrid, THREADS, SMEM_TOTAL>>>(x, SEQ_T * FDIM,
        ahb[1], alb[1], ahb[0], alb[0], 1);
    step = 1;
    for (int t = 1; t < SEQ_T; t++, step++)
        lstm_step_mma<<<sgrid, THREADS, SMEM_TOTAL>>>(x + t * FDIM, SEQ_T * FDIM,
            ahb[(step - 1) & 1], alb[(step - 1) & 1],
            ahb[step & 1], alb[step & 1], 0);

    pred_kernel<<<pblocks, 256>>>(h_ptr, Wd, bd, out, NOUT * FDIM, pred_ptr);

    for (int s = 1; s < NOUT; s++, step++) {
        lstm_step_mma<<<sgrid, THREADS, SMEM_TOTAL>>>(pred_ptr, FDIM,
            ahb[(step - 1) & 1], alb[(step - 1) & 1],
            ahb[step & 1], alb[step & 1], 0);
        pred_kernel<<<pblocks, 256>>>(h_ptr, Wd, bd, out + s * FDIM,
                                      NOUT * FDIM, pred_ptr);
    }
}

// round 8
// speedup vs baseline: 2.4328x; 2.4328x over previous
#include <cuda_runtime.h>
#include <cuda_bf16.h>
#include <cstdint>

// ---------------------------------------------------------------------------
// FeedBack LSTM via mma.sync bf16 (baseline PTX; sm_103 target, no 'a' feats).
// R8: register-direct GEMM. Both operands stored in gmem pre-arranged in the
// exact mma.sync fragment layout (A written by our own epilogue, B prepped),
// so the K-loop is LDG.128 -> HMMA with NO smem tiles / cp.async / ldmatrix /
// __syncthreads. 3-term bf16 hi/lo split, fp32 accum, fused LSTM cell update.
// B=16384, T=48, F=4, UNITS=256 (z width 1024), OUT_STEPS=24.
// ---------------------------------------------------------------------------

namespace {
constexpr int BATCH = 16384;
constexpr int SEQ_T = 48;
constexpr int FDIM  = 4;
constexpr int NU    = 256;
constexpr int NOUT  = 24;
constexpr int Z4    = 1024;

constexpr int THREADS = 256;   // 8 warps: 4 m-warps x 2 n-warps (warp 32x64)
constexpr int NM16 = BATCH / 16;        // 1024 m16 blocks
constexpr int NKC  = NU / 16;           // 16 k16 chunks
constexpr int NT8  = Z4 / 8;            // 128 n8 tiles
}

// ---------------- device state (allocation-free) ----------------
// A fragments: [buf][m16blk(1024)][kchunk(16)][lane(32)] : uint4 = a0..a3
__device__ __align__(16) uint4 g_a4h[2 * NM16 * NKC * 32];
__device__ __align__(16) uint4 g_a4l[2 * NM16 * NKC * 32];
// B fragments: [ntile(128)][kchunk(16)][lane(32)] : uint4 = (b0h,b1h,b0l,b1l)
__device__ __align__(16) uint4 g_b4[NT8 * NKC * 32];
// permuted Wx / b (fp32)
__device__ float g_wxp[FDIM * Z4];
__device__ float g_bp[Z4];
// fp32 state
__device__ float g_h[BATCH * NU];
__device__ float g_c[BATCH * NU];
__device__ __align__(16) float g_pred[BATCH * FDIM];

// ---------------- helpers ----------------
__device__ __forceinline__ void mma16816(float* d, const uint32_t* a,
                                         const uint32_t* b) {
    asm volatile(
        "mma.sync.aligned.m16n8k16.row.col.f32.bf16.bf16.f32 "
        "{%0,%1,%2,%3}, {%4,%5,%6,%7}, {%8,%9}, {%0,%1,%2,%3};"
        : "+f"(d[0]), "+f"(d[1]), "+f"(d[2]), "+f"(d[3])
        : "r"(a[0]), "r"(a[1]), "r"(a[2]), "r"(a[3]), "r"(b[0]), "r"(b[1]));
}
__device__ __forceinline__ float sigmoid_acc(float x) {
    return 0.5f * (1.0f + tanhf(0.5f * x));
}
__device__ __forceinline__ uint32_t pack_bf16(float a, float b) {
    __nv_bfloat16 x = __float2bfloat16(a);
    __nv_bfloat16 y = __float2bfloat16(b);
    return (uint32_t)__bfloat16_as_ushort(x) |
           ((uint32_t)__bfloat16_as_ushort(y) << 16);
}
__device__ __forceinline__ void split_bf16(float v, float& hi_f, uint16_t& hi,
                                           uint16_t& lo) {
    __nv_bfloat16 h = __float2bfloat16(v);
    hi_f = __bfloat162float(h);
    hi = __bfloat16_as_ushort(h);
    lo = __bfloat16_as_ushort(__float2bfloat16(v - hi_f));
}

// ---------------- prep kernels ----------------
// Permuted z-col p: nt=p>>7, loc=p&127; wn=loc>>6, g=(loc>>4)&3, ul=loc&15;
// unit u = nt*32 + wn*16 + ul; original col oc = g*256 + u.
// k dimension: kpos = unit index (identity; see A-frag epilogue mapping).
__global__ void prep_b4(const float* __restrict__ Wh) {
    int idx = blockIdx.x * 256 + threadIdx.x;   // 65536 = 128 nt8 x 16 kc x 32
    int lane = idx & 31;
    int kc   = (idx >> 5) & 15;
    int ntile = idx >> 9;
    int q = lane >> 2, s = lane & 3;
    int p = ntile * 8 + q;                      // permuted z-col (n of frag)
    int nt = p >> 7, loc = p & 127;
    int wn = loc >> 6, g = (loc >> 4) & 3, ul = loc & 15;
    int oc = g * 256 + nt * 32 + wn * 16 + ul;  // original Wh column
    int k0 = kc * 16 + 2 * s;
    float v0 = Wh[(k0    ) * Z4 + oc];
    float v1 = Wh[(k0 + 1) * Z4 + oc];
    float v8 = Wh[(k0 + 8) * Z4 + oc];
    float v9 = Wh[(k0 + 9) * Z4 + oc];
    float f0, f1, f8, f9;
    uint16_t h0, h1, h8, h9, l0, l1, l8, l9;
    split_bf16(v0, f0, h0, l0);
    split_bf16(v1, f1, h1, l1);
    split_bf16(v8, f8, h8, l8);
    split_bf16(v9, f9, h9, l9);
    uint4 r;
    r.x = (uint32_t)h0 | ((uint32_t)h1 << 16);  // b0 hi
    r.y = (uint32_t)h8 | ((uint32_t)h9 << 16);  // b1 hi
    r.z = (uint32_t)l0 | ((uint32_t)l1 << 16);  // b0 lo
    r.w = (uint32_t)l8 | ((uint32_t)l9 << 16);  // b1 lo
    g_b4[idx] = r;
}

__global__ void prep_wxb(const float* __restrict__ Wx, const float* __restrict__ b) {
    int p = threadIdx.x;                        // 0..1023
    int nt = p >> 7, loc = p & 127;
    int wn = loc >> 6, g = (loc >> 4) & 3, ul = loc & 15;
    int oc = g * 256 + nt * 32 + wn * 16 + ul;
    g_bp[p] = b[oc];
    #pragma unroll
    for (int f = 0; f < FDIM; f++)
        g_wxp[f * Z4 + p] = Wx[f * Z4 + oc];
}

// ---------------- main timestep kernel ----------------
__global__ void __launch_bounds__(THREADS)
lstm_step_reg(const float* __restrict__ xt, int xstride,
              const uint4* __restrict__ a4h_in,
              const uint4* __restrict__ a4l_in,
              uint4* __restrict__ a4h_out,
              uint4* __restrict__ a4l_out,
              int first)
{
    __shared__ float wx_s[4 * 128];
    __shared__ float bp_s[128];

    const int tid  = threadIdx.x;
    const int lane = tid & 31;
    const int wid  = tid >> 5;
    const int wm   = wid & 3;        // m-warp: rows wm*32..+32
    const int wn   = wid >> 2;       // n-warp: permuted cols wn*64..+64
    const int nt   = blockIdx.x;     // 0..7
    const int rt   = blockIdx.y;     // 0..127
    const int rbase = rt * 128;

    for (int i = tid; i < 4 * 128; i += THREADS) {
        int f = i >> 7, j = i & 127;
        wx_s[i] = g_wxp[f * Z4 + nt * 128 + j];
    }
    if (tid < 128) bp_s[tid] = g_bp[nt * 128 + tid];
    __syncthreads();

    // accumulators d[mi][ni][frag]; ni = g*2 + sub
    float d[2][8][4];
    #pragma unroll
    for (int mi = 0; mi < 2; mi++)
        #pragma unroll
        for (int ni = 0; ni < 8; ni++)
            #pragma unroll
            for (int r = 0; r < 4; r++)
                d[mi][ni][r] = 0.0f;

    if (!first) {
        // fragment base indices (elements of uint4 arrays)
        // A: ((rt*8 + wm*2 + mi)*16 + kc)*32 + lane
        // B: ((nt*16 + wn*8 + ni)*16 + kc)*32 + lane
        const int aBase = ((rt * 8 + wm * 2) * 16) * 32 + lane;
        const int bBase = ((nt * 16 + wn * 8) * 16) * 32 + lane;

        uint4 Ah[2][2], Al[2][2], Bq[2][8];
        #pragma unroll
        for (int mi = 0; mi < 2; mi++) {
            Ah[0][mi] = a4h_in[aBase + mi * 512];
            Al[0][mi] = a4l_in[aBase + mi * 512];
        }
        #pragma unroll
        for (int ni = 0; ni < 8; ni++)
            Bq[0][ni] = g_b4[bBase + ni * 512];

        #pragma unroll
        for (int kc = 0; kc < NKC; kc++) {
            const int cur = kc & 1, nx = cur ^ 1;
            if (kc < NKC - 1) {
                const int ko = (kc + 1) * 32;
                #pragma unroll
                for (int mi = 0; mi < 2; mi++) {
                    Ah[nx][mi] = a4h_in[aBase + mi * 512 + ko];
                    Al[nx][mi] = a4l_in[aBase + mi * 512 + ko];
                }
                #pragma unroll
                for (int ni = 0; ni < 8; ni++)
                    Bq[nx][ni] = g_b4[bBase + ni * 512 + ko];
            }
            #pragma unroll
            for (int mi = 0; mi < 2; mi++) {
                const uint32_t* ah = reinterpret_cast<const uint32_t*>(&Ah[cur][mi]);
                const uint32_t* al = reinterpret_cast<const uint32_t*>(&Al[cur][mi]);
                #pragma unroll
                for (int ni = 0; ni < 8; ni++) {
                    const uint32_t bh[2] = {Bq[cur][ni].x, Bq[cur][ni].y};
                    const uint32_t bl[2] = {Bq[cur][ni].z, Bq[cur][ni].w};
                    mma16816(d[mi][ni], ah, bh);
                    mma16816(d[mi][ni], al, bh);
                    mma16816(d[mi][ni], ah, bl);
                }
            }
        }
    }

    // ---- epilogue: z -> gates -> c,h; write fp32 h + A-frag hi/lo ----
    const int q  = lane >> 2;
    const int s4 = lane & 3;
    const int kself = nt * 2 + wn;   // kchunk this warp's units belong to
    #pragma unroll
    for (int mi = 0; mi < 2; mi++) {
        float hn[2][2][2];           // [rh][sub][par]
        #pragma unroll
        for (int rh = 0; rh < 2; rh++) {
            const int row = rbase + wm * 32 + mi * 16 + q + rh * 8;
            const float4 xv = *reinterpret_cast<const float4*>(
                &xt[(long)row * xstride]);
            #pragma unroll
            for (int sub = 0; sub < 2; sub++) {
                const int ul0 = sub * 8 + s4 * 2;             // even unit
                const int u   = nt * 32 + wn * 16 + ul0;
                const int ci  = row * NU + u;
                float2 cold = first ? make_float2(0.f, 0.f)
                    : *reinterpret_cast<const float2*>(&g_c[ci]);
                const float coldv[2] = {cold.x, cold.y};
                float cn2[2], hn2[2];
                #pragma unroll
                for (int par = 0; par < 2; par++) {
                    float z[4];
                    #pragma unroll
                    for (int g = 0; g < 4; g++) {
                        const int nl = wn * 64 + g * 16 + ul0 + par;
                        float zz = bp_s[nl] + d[mi][g * 2 + sub][rh * 2 + par];
                        zz = fmaf(xv.x, wx_s[nl],       zz);
                        zz = fmaf(xv.y, wx_s[128 + nl], zz);
                        zz = fmaf(xv.z, wx_s[256 + nl], zz);
                        zz = fmaf(xv.w, wx_s[384 + nl], zz);
                        z[g] = zz;
                    }
                    const float ig = sigmoid_acc(z[0]);
                    const float fg = sigmoid_acc(z[1]);
                    const float gg = tanhf(z[2]);
                    const float og = sigmoid_acc(z[3]);
                    const float cn = fg * coldv[par] + ig * gg;
                    const float hv = og * tanhf(cn);
                    cn2[par] = cn;
                    hn2[par] = hv;
                    hn[rh][sub][par] = hv;
                }
                *reinterpret_cast<float2*>(&g_c[ci]) = make_float2(cn2[0], cn2[1]);
                *reinterpret_cast<float2*>(&g_h[ci]) = make_float2(hn2[0], hn2[1]);
            }
        }
        // Pack this thread's 8 h values as next step's A fragment:
        // a0=(q, 2s,2s+1)         = hn[0][0][0..1]
        // a1=(q+8, 2s,2s+1)       = hn[1][0][0..1]
        // a2=(q, 8+2s,8+2s+1)     = hn[0][1][0..1]
        // a3=(q+8, 8+2s,8+2s+1)   = hn[1][1][0..1]
        uint4 fh, fl;
        {
            float t0h, t1h;
            __nv_bfloat16 b0, b1;
            // a0
            b0 = __float2bfloat16(hn[0][0][0]); b1 = __float2bfloat16(hn[0][0][1]);
            t0h = __bfloat162float(b0); t1h = __bfloat162float(b1);
            fh.x = (uint32_t)__bfloat16_as_ushort(b0) |
                   ((uint32_t)__bfloat16_as_ushort(b1) << 16);
            fl.x = pack_bf16(hn[0][0][0] - t0h, hn[0][0][1] - t1h);
            // a1
            b0 = __float2bfloat16(hn[1][0][0]); b1 = __float2bfloat16(hn[1][0][1]);
            t0h = __bfloat162float(b0); t1h = __bfloat162float(b1);
            fh.y = (uint32_t)__bfloat16_as_ushort(b0) |
                   ((uint32_t)__bfloat16_as_ushort(b1) << 16);
            fl.y = pack_bf16(hn[1][0][0] - t0h, hn[1][0][1] - t1h);
            // a2
            b0 = __float2bfloat16(hn[0][1][0]); b1 = __float2bfloat16(hn[0][1][1]);
            t0h = __bfloat162float(b0); t1h = __bfloat162float(b1);
            fh.z = (uint32_t)__bfloat16_as_ushort(b0) |
                   ((uint32_t)__bfloat16_as_ushort(b1) << 16);
            fl.z = pack_bf16(hn[0][1][0] - t0h, hn[0][1][1] - t1h);
            // a3
            b0 = __float2bfloat16(hn[1][1][0]); b1 = __float2bfloat16(hn[1][1][1]);
            t0h = __bfloat162float(b0); t1h = __bfloat162float(b1);
            fh.w = (uint32_t)__bfloat16_as_ushort(b0) |
                   ((uint32_t)__bfloat16_as_ushort(b1) << 16);
            fl.w = pack_bf16(hn[1][1][0] - t0h, hn[1][1][1] - t1h);
        }
        const int oi = ((rt * 8 + wm * 2 + mi) * 16 + kself) * 32 + lane;
        a4h_out[oi] = fh;
        a4l_out[oi] = fl;
    }
}

// pred = h @ Wd + bd ; writes output slice and feedback buffer.
__global__ void pred_kernel(const float* __restrict__ h,
                            const float* __restrict__ Wd,
                            const float* __restrict__ bd,
                            float* __restrict__ out, int ostride,
                            float* __restrict__ pred)
{
    const int gwarp = (blockIdx.x * blockDim.x + threadIdx.x) >> 5;
    const int lane  = threadIdx.x & 31;
    if (gwarp >= BATCH) return;

    const float* hrow = h + gwarp * NU;
    float a0 = 0.f, a1 = 0.f, a2 = 0.f, a3 = 0.f;
    #pragma unroll
    for (int k = lane; k < NU; k += 32) {
        float hv = hrow[k];
        float4 wv = *reinterpret_cast<const float4*>(&Wd[k * 4]);
        a0 = fmaf(hv, wv.x, a0);
        a1 = fmaf(hv, wv.y, a1);
        a2 = fmaf(hv, wv.z, a2);
        a3 = fmaf(hv, wv.w, a3);
    }
    #pragma unroll
    for (int off = 16; off > 0; off >>= 1) {
        a0 += __shfl_down_sync(0xffffffffu, a0, off);
        a1 += __shfl_down_sync(0xffffffffu, a1, off);
        a2 += __shfl_down_sync(0xffffffffu, a2, off);
        a3 += __shfl_down_sync(0xffffffffu, a3, off);
    }
    if (lane == 0) {
        float4 r = make_float4(a0 + bd[0], a1 + bd[1], a2 + bd[2], a3 + bd[3]);
        *reinterpret_cast<float4*>(&out[(long)gwarp * ostride]) = r;
        *reinterpret_cast<float4*>(&pred[gwarp * 4]) = r;
    }
}

extern "C" void kernel_launch(void* const* d_in, const int* in_sizes, int n_in,
                              void* d_out, int out_size)
{
    const float* x  = (const float*)d_in[0];
    const float* Wx = (const float*)d_in[1];
    const float* Wh = (const float*)d_in[2];
    const float* b  = (const float*)d_in[3];
    const float* Wd = (const float*)d_in[4];
    const float* bd = (const float*)d_in[5];
    float* out = (float*)d_out;

    float* pred_ptr = nullptr;
    float* h_ptr = nullptr;
    uint4* ah = nullptr;
    uint4* al = nullptr;
    cudaGetSymbolAddress((void**)&pred_ptr, g_pred);
    cudaGetSymbolAddress((void**)&h_ptr, g_h);
    cudaGetSymbolAddress((void**)&ah, g_a4h);
    cudaGetSymbolAddress((void**)&al, g_a4l);
    const long BUFQ = (long)NM16 * NKC * 32;
    uint4* ahb[2] = {ah, ah + BUFQ};
    uint4* alb[2] = {al, al + BUFQ};

    // weight prep (re-run every replay -> deterministic)
    prep_b4<<<256, 256>>>(Wh);
    prep_wxb<<<1, 1024>>>(Wx, b);

    const dim3 sgrid(8, 128);
    const int pblocks = (BATCH * 32) / 256;

    int step = 0;
    lstm_step_reg<<<sgrid, THREADS>>>(x, SEQ_T * FDIM,
        ahb[1], alb[1], ahb[0], alb[0], 1);
    step = 1;
    for (int t = 1; t < SEQ_T; t++, step++)
        lstm_step_reg<<<sgrid, THREADS>>>(x + t * FDIM, SEQ_T * FDIM,
            ahb[(step - 1) & 1], alb[(step - 1) & 1],
            ahb[step & 1], alb[step & 1], 0);

    pred_kernel<<<pblocks, 256>>>(h_ptr, Wd, bd, out, NOUT * FDIM, pred_ptr);

    for (int s = 1; s < NOUT; s++, step++) {
        lstm_step_reg<<<sgrid, THREADS>>>(pred_ptr, FDIM,
            ahb[(step - 1) & 1], alb[(step - 1) & 1],
            ahb[step & 1], alb[step & 1], 0);
        pred_kernel<<<pblocks, 256>>>(h_ptr, Wd, bd, out + s * FDIM,
                                      NOUT * FDIM, pred_ptr);
    }
}

// round 9
// speedup vs baseline: 3.3044x; 1.3583x over previous
#include <cuda_runtime.h>
#include <cuda_bf16.h>
#include <cstdint>

// ---------------------------------------------------------------------------
// FeedBack LSTM via mma.sync bf16 (baseline PTX; sm_103 target, no 'a' feats).
// R9: register-direct GEMM (no smem tiles / no barriers in K-loop), warp tile
// 32x32 so 2 CTAs/SM fit (16 warps/SM) for latency hiding. 3-term bf16 hi/lo
// split, fp32 accum, fused LSTM cell update; A fragments written by epilogue
// directly in mma.sync layout (identity map).
// B=16384, T=48, F=4, UNITS=256 (z width 1024), OUT_STEPS=24.
// ---------------------------------------------------------------------------

namespace {
constexpr int BATCH = 16384;
constexpr int SEQ_T = 48;
constexpr int FDIM  = 4;
constexpr int NU    = 256;
constexpr int NOUT  = 24;
constexpr int Z4    = 1024;

constexpr int THREADS = 256;   // 8 warps: 2 m-warps x 4 n-warps (warp 32x32)
constexpr int NM16 = BATCH / 16;        // 1024 m16 blocks
constexpr int NKC  = NU / 16;           // 16 k16 chunks
constexpr int NT8  = Z4 / 8;            // 128 n8 tiles
}

// ---------------- device state (allocation-free) ----------------
// A fragments: [buf][m16blk(1024)][kchunk(16)][lane(32)] : uint4 = a0..a3
__device__ __align__(16) uint4 g_a4h[2 * NM16 * NKC * 32];
__device__ __align__(16) uint4 g_a4l[2 * NM16 * NKC * 32];
// B fragments: [ntile(128)][kchunk(16)][lane(32)] : uint4 = (b0h,b1h,b0l,b1l)
__device__ __align__(16) uint4 g_b4[NT8 * NKC * 32];
// permuted Wx / b (fp32)
__device__ float g_wxp[FDIM * Z4];
__device__ float g_bp[Z4];
// fp32 state
__device__ float g_h[BATCH * NU];
__device__ float g_c[BATCH * NU];
__device__ __align__(16) float g_pred[BATCH * FDIM];

// ---------------- helpers ----------------
__device__ __forceinline__ void mma16816(float* d, const uint32_t* a,
                                         const uint32_t* b) {
    asm volatile(
        "mma.sync.aligned.m16n8k16.row.col.f32.bf16.bf16.f32 "
        "{%0,%1,%2,%3}, {%4,%5,%6,%7}, {%8,%9}, {%0,%1,%2,%3};"
        : "+f"(d[0]), "+f"(d[1]), "+f"(d[2]), "+f"(d[3])
        : "r"(a[0]), "r"(a[1]), "r"(a[2]), "r"(a[3]), "r"(b[0]), "r"(b[1]));
}
__device__ __forceinline__ float sigmoid_acc(float x) {
    return 0.5f * (1.0f + tanhf(0.5f * x));
}
__device__ __forceinline__ uint32_t pack_bf16(float a, float b) {
    __nv_bfloat16 x = __float2bfloat16(a);
    __nv_bfloat16 y = __float2bfloat16(b);
    return (uint32_t)__bfloat16_as_ushort(x) |
           ((uint32_t)__bfloat16_as_ushort(y) << 16);
}
__device__ __forceinline__ void split_bf16(float v, float& hi_f, uint16_t& hi,
                                           uint16_t& lo) {
    __nv_bfloat16 h = __float2bfloat16(v);
    hi_f = __bfloat162float(h);
    hi = __bfloat16_as_ushort(h);
    lo = __bfloat16_as_ushort(__float2bfloat16(v - hi_f));
}

// ---------------- prep kernels ----------------
// Permuted z-col p: nt=p>>7, loc=p&127; wn=loc>>5, g=(loc>>3)&3, ul=loc&7;
// unit u = nt*32 + wn*8 + ul; original col oc = g*256 + u.
__global__ void prep_b4(const float* __restrict__ Wh) {
    int idx = blockIdx.x * 256 + threadIdx.x;   // 65536 = 128 nt8 x 16 kc x 32
    int lane = idx & 31;
    int kc   = (idx >> 5) & 15;
    int ntile = idx >> 9;
    int q = lane >> 2, s = lane & 3;
    int p = ntile * 8 + q;                      // permuted z-col (n of frag)
    int nt = p >> 7, loc = p & 127;
    int wn = loc >> 5, g = (loc >> 3) & 3, ul = loc & 7;
    int oc = g * 256 + nt * 32 + wn * 8 + ul;   // original Wh column
    int k0 = kc * 16 + 2 * s;
    float v0 = Wh[(k0    ) * Z4 + oc];
    float v1 = Wh[(k0 + 1) * Z4 + oc];
    float v8 = Wh[(k0 + 8) * Z4 + oc];
    float v9 = Wh[(k0 + 9) * Z4 + oc];
    float f0, f1, f8, f9;
    uint16_t h0, h1, h8, h9, l0, l1, l8, l9;
    split_bf16(v0, f0, h0, l0);
    split_bf16(v1, f1, h1, l1);
    split_bf16(v8, f8, h8, l8);
    split_bf16(v9, f9, h9, l9);
    uint4 r;
    r.x = (uint32_t)h0 | ((uint32_t)h1 << 16);  // b0 hi
    r.y = (uint32_t)h8 | ((uint32_t)h9 << 16);  // b1 hi
    r.z = (uint32_t)l0 | ((uint32_t)l1 << 16);  // b0 lo
    r.w = (uint32_t)l8 | ((uint32_t)l9 << 16);  // b1 lo
    g_b4[idx] = r;
}

__global__ void prep_wxb(const float* __restrict__ Wx, const float* __restrict__ b) {
    int p = threadIdx.x;                        // 0..1023
    int nt = p >> 7, loc = p & 127;
    int wn = loc >> 5, g = (loc >> 3) & 3, ul = loc & 7;
    int oc = g * 256 + nt * 32 + wn * 8 + ul;
    g_bp[p] = b[oc];
    #pragma unroll
    for (int f = 0; f < FDIM; f++)
        g_wxp[f * Z4 + p] = Wx[f * Z4 + oc];
}

// ---------------- main timestep kernel ----------------
__global__ void __launch_bounds__(THREADS, 2)
lstm_step_reg(const float* __restrict__ xt, int xstride,
              const uint4* __restrict__ a4h_in,
              const uint4* __restrict__ a4l_in,
              uint4* __restrict__ a4h_out,
              uint4* __restrict__ a4l_out,
              int first)
{
    __shared__ float wx_s[4 * 128];
    __shared__ float bp_s[128];

    const int tid  = threadIdx.x;
    const int lane = tid & 31;
    const int wid  = tid >> 5;
    const int wm   = wid & 1;        // m-warp: rows wm*32..+32 (of 64)
    const int wn   = wid >> 1;       // n-warp: permuted cols wn*32..+32
    const int rt   = blockIdx.x;     // 0..255 (64 rows each)
    const int nt   = blockIdx.y;     // 0..7

    for (int i = tid; i < 4 * 128; i += THREADS) {
        int f = i >> 7, j = i & 127;
        wx_s[i] = g_wxp[f * Z4 + nt * 128 + j];
    }
    if (tid < 128) bp_s[tid] = g_bp[nt * 128 + tid];
    __syncthreads();

    // accumulators d[mi][gate][frag]
    float d[2][4][4];
    #pragma unroll
    for (int mi = 0; mi < 2; mi++)
        #pragma unroll
        for (int g = 0; g < 4; g++)
            #pragma unroll
            for (int r = 0; r < 4; r++)
                d[mi][g][r] = 0.0f;

    if (!first) {
        // A: ((rt*4 + wm*2 + mi)*16 + kc)*32 + lane   (uint4 units)
        // B: ((nt*16 + wn*4 + g)*16 + kc)*32 + lane
        const int aBase = ((rt * 4 + wm * 2) * 16) * 32 + lane;
        const int bBase = ((nt * 16 + wn * 4) * 16) * 32 + lane;

        uint4 Ah[2][2], Al[2][2], Bq[2][4];
        #pragma unroll
        for (int mi = 0; mi < 2; mi++) {
            Ah[0][mi] = a4h_in[aBase + mi * 512];
            Al[0][mi] = a4l_in[aBase + mi * 512];
        }
        #pragma unroll
        for (int g = 0; g < 4; g++)
            Bq[0][g] = g_b4[bBase + g * 512];

        #pragma unroll
        for (int kc = 0; kc < NKC; kc++) {
            const int cur = kc & 1, nx = cur ^ 1;
            if (kc < NKC - 1) {
                const int ko = (kc + 1) * 32;
                #pragma unroll
                for (int mi = 0; mi < 2; mi++) {
                    Ah[nx][mi] = a4h_in[aBase + mi * 512 + ko];
                    Al[nx][mi] = a4l_in[aBase + mi * 512 + ko];
                }
                #pragma unroll
                for (int g = 0; g < 4; g++)
                    Bq[nx][g] = g_b4[bBase + g * 512 + ko];
            }
            #pragma unroll
            for (int mi = 0; mi < 2; mi++) {
                const uint32_t* ah = reinterpret_cast<const uint32_t*>(&Ah[cur][mi]);
                const uint32_t* al = reinterpret_cast<const uint32_t*>(&Al[cur][mi]);
                #pragma unroll
                for (int g = 0; g < 4; g++) {
                    const uint32_t bh[2] = {Bq[cur][g].x, Bq[cur][g].y};
                    const uint32_t bl[2] = {Bq[cur][g].z, Bq[cur][g].w};
                    mma16816(d[mi][g], ah, bh);
                    mma16816(d[mi][g], al, bh);
                    mma16816(d[mi][g], ah, bl);
                }
            }
        }
    }

    // ---- epilogue: z -> gates -> c,h; write fp32 h + A-frag hi/lo ----
    const int q  = lane >> 2;
    const int s4 = lane & 3;
    const int kcs = nt * 2 + (wn >> 1);     // kchunk of this warp's units
    const int slotbase = (wn & 1) * 2;      // a0a1 (k<8) or a2a3 (k>=8)
    uint32_t* ah32 = reinterpret_cast<uint32_t*>(a4h_out);
    uint32_t* al32 = reinterpret_cast<uint32_t*>(a4l_out);

    #pragma unroll
    for (int mi = 0; mi < 2; mi++) {
        float hn[2][2];                      // [rh][par]
        #pragma unroll
        for (int rh = 0; rh < 2; rh++) {
            const int row = rt * 64 + wm * 32 + mi * 16 + q + rh * 8;
            const float4 xv = *reinterpret_cast<const float4*>(
                &xt[(long)row * xstride]);
            const int ci = row * NU + nt * 32 + wn * 8 + s4 * 2;
            float2 cold = first ? make_float2(0.f, 0.f)
                : *reinterpret_cast<const float2*>(&g_c[ci]);
            const float coldv[2] = {cold.x, cold.y};
            float cn2[2], hn2[2];
            #pragma unroll
            for (int par = 0; par < 2; par++) {
                float z[4];
                #pragma unroll
                for (int g = 0; g < 4; g++) {
                    const int nl = wn * 32 + g * 8 + s4 * 2 + par;
                    float zz = bp_s[nl] + d[mi][g][rh * 2 + par];
                    zz = fmaf(xv.x, wx_s[nl],       zz);
                    zz = fmaf(xv.y, wx_s[128 + nl], zz);
                    zz = fmaf(xv.z, wx_s[256 + nl], zz);
                    zz = fmaf(xv.w, wx_s[384 + nl], zz);
                    z[g] = zz;
                }
                const float ig = sigmoid_acc(z[0]);
                const float fg = sigmoid_acc(z[1]);
                const float gg = tanhf(z[2]);
                const float og = sigmoid_acc(z[3]);
                const float cn = fg * coldv[par] + ig * gg;
                const float hv = og * tanhf(cn);
                cn2[par] = cn;
                hn2[par] = hv;
                hn[rh][par] = hv;
            }
            *reinterpret_cast<float2*>(&g_c[ci]) = make_float2(cn2[0], cn2[1]);
            *reinterpret_cast<float2*>(&g_h[ci]) = make_float2(hn2[0], hn2[1]);
        }
        // A-fragment store: this thread's (par0,par1) pair is frag cols
        // 2s,2s+1 (wn even -> a0/a1) or 8+2s,8+2s+1 (wn odd -> a2/a3);
        // rh=0 -> row q (a0/a2), rh=1 -> row q+8 (a1/a3).
        const int m16blk = rt * 4 + wm * 2 + mi;
        const int fb = ((m16blk * 16 + kcs) * 32 + lane) * 4 + slotbase;
        uint2 fh, fl;
        {
            __nv_bfloat16 b0 = __float2bfloat16(hn[0][0]);
            __nv_bfloat16 b1 = __float2bfloat16(hn[0][1]);
            fh.x = (uint32_t)__bfloat16_as_ushort(b0) |
                   ((uint32_t)__bfloat16_as_ushort(b1) << 16);
            fl.x = pack_bf16(hn[0][0] - __bfloat162float(b0),
                             hn[0][1] - __bfloat162float(b1));
            b0 = __float2bfloat16(hn[1][0]);
            b1 = __float2bfloat16(hn[1][1]);
            fh.y = (uint32_t)__bfloat16_as_ushort(b0) |
                   ((uint32_t)__bfloat16_as_ushort(b1) << 16);
            fl.y = pack_bf16(hn[1][0] - __bfloat162float(b0),
                             hn[1][1] - __bfloat162float(b1));
        }
        *reinterpret_cast<uint2*>(&ah32[fb]) = fh;
        *reinterpret_cast<uint2*>(&al32[fb]) = fl;
    }
}

// pred = h @ Wd + bd ; writes output slice and feedback buffer.
__global__ void pred_kernel(const float* __restrict__ h,
                            const float* __restrict__ Wd,
                            const float* __restrict__ bd,
                            float* __restrict__ out, int ostride,
                            float* __restrict__ pred)
{
    const int gwarp = (blockIdx.x * blockDim.x + threadIdx.x) >> 5;
    const int lane  = threadIdx.x & 31;
    if (gwarp >= BATCH) return;

    const float* hrow = h + gwarp * NU;
    float a0 = 0.f, a1 = 0.f, a2 = 0.f, a3 = 0.f;
    #pragma unroll
    for (int k = lane; k < NU; k += 32) {
        float hv = hrow[k];
        float4 wv = *reinterpret_cast<const float4*>(&Wd[k * 4]);
        a0 = fmaf(hv, wv.x, a0);
        a1 = fmaf(hv, wv.y, a1);
        a2 = fmaf(hv, wv.z, a2);
        a3 = fmaf(hv, wv.w, a3);
    }
    #pragma unroll
    for (int off = 16; off > 0; off >>= 1) {
        a0 += __shfl_down_sync(0xffffffffu, a0, off);
        a1 += __shfl_down_sync(0xffffffffu, a1, off);
        a2 += __shfl_down_sync(0xffffffffu, a2, off);
        a3 += __shfl_down_sync(0xffffffffu, a3, off);
    }
    if (lane == 0) {
        float4 r = make_float4(a0 + bd[0], a1 + bd[1], a2 + bd[2], a3 + bd[3]);
        *reinterpret_cast<float4*>(&out[(long)gwarp * ostride]) = r;
        *reinterpret_cast<float4*>(&pred[gwarp * 4]) = r;
    }
}

extern "C" void kernel_launch(void* const* d_in, const int* in_sizes, int n_in,
                              void* d_out, int out_size)
{
    const float* x  = (const float*)d_in[0];
    const float* Wx = (const float*)d_in[1];
    const float* Wh = (const float*)d_in[2];
    const float* b  = (const float*)d_in[3];
    const float* Wd = (const float*)d_in[4];
    const float* bd = (const float*)d_in[5];
    float* out = (float*)d_out;

    float* pred_ptr = nullptr;
    float* h_ptr = nullptr;
    uint4* ah = nullptr;
    uint4* al = nullptr;
    cudaGetSymbolAddress((void**)&pred_ptr, g_pred);
    cudaGetSymbolAddress((void**)&h_ptr, g_h);
    cudaGetSymbolAddress((void**)&ah, g_a4h);
    cudaGetSymbolAddress((void**)&al, g_a4l);
    const long BUFQ = (long)NM16 * NKC * 32;
    uint4* ahb[2] = {ah, ah + BUFQ};
    uint4* alb[2] = {al, al + BUFQ};

    // weight prep (re-run every replay -> deterministic)
    prep_b4<<<256, 256>>>(Wh);
    prep_wxb<<<1, 1024>>>(Wx, b);

    const dim3 sgrid(256, 8);          // (row tiles, unit tiles) — rt fastest
    const int pblocks = (BATCH * 32) / 256;

    int step = 0;
    lstm_step_reg<<<sgrid, THREADS>>>(x, SEQ_T * FDIM,
        ahb[1], alb[1], ahb[0], alb[0], 1);
    step = 1;
    for (int t = 1; t < SEQ_T; t++, step++)
        lstm_step_reg<<<sgrid, THREADS>>>(x + t * FDIM, SEQ_T * FDIM,
            ahb[(step - 1) & 1], alb[(step - 1) & 1],
            ahb[step & 1], alb[step & 1], 0);

    pred_kernel<<<pblocks, 256>>>(h_ptr, Wd, bd, out, NOUT * FDIM, pred_ptr);

    for (int s = 1; s < NOUT; s++, step++) {
        lstm_step_reg<<<sgrid, THREADS>>>(pred_ptr, FDIM,
            ahb[(step - 1) & 1], alb[(step - 1) & 1],
            ahb[step & 1], alb[step & 1], 0);
        pred_kernel<<<pblocks, 256>>>(h_ptr, Wd, bd, out + s * FDIM,
                                      NOUT * FDIM, pred_ptr);
    }
}

// round 10
// speedup vs baseline: 4.0846x; 1.2361x over previous
#include <cuda_runtime.h>
#include <cuda_fp16.h>
#include <cstdint>

// ---------------------------------------------------------------------------
// FeedBack LSTM via mma.sync fp16 (baseline PTX; sm_103 target, no 'a' feats).
// R10: register-direct GEMM (no smem tiles / no barriers in K-loop),
// fp16 hi/lo 2-term split: z = Ah·Bh + Al·Bh (A=h kept to ~22 bits, B=Wh to
// 11 bits; dropped A·Bl term ~2^-11/step, contractive recurrence -> ~1e-4).
// Warp tile 32x32, 2 CTAs/SM. A fragments written by the epilogue directly in
// mma.sync fragment layout (identity map). Fused LSTM cell update.
// B=16384, T=48, F=4, UNITS=256 (z width 1024), OUT_STEPS=24.
// ---------------------------------------------------------------------------

namespace {
constexpr int BATCH = 16384;
constexpr int SEQ_T = 48;
constexpr int FDIM  = 4;
constexpr int NU    = 256;
constexpr int NOUT  = 24;
constexpr int Z4    = 1024;

constexpr int THREADS = 256;   // 8 warps: 2 m-warps x 4 n-warps (warp 32x32)
constexpr int NM16 = BATCH / 16;        // 1024 m16 blocks
constexpr int NKC  = NU / 16;           // 16 k16 chunks
constexpr int NT8  = Z4 / 8;            // 128 n8 tiles
}

// ---------------- device state (allocation-free) ----------------
// A fragments (fp16): [buf][m16blk(1024)][kchunk(16)][lane(32)] : uint4=a0..a3
__device__ __align__(16) uint4 g_a4h[2 * NM16 * NKC * 32];
__device__ __align__(16) uint4 g_a4l[2 * NM16 * NKC * 32];
// B fragments (fp16 hi only): [ntile(128)][kchunk(16)][lane(32)] : uint2=b0,b1
__device__ __align__(16) uint2 g_b2[NT8 * NKC * 32];
// permuted Wx / b (fp32)
__device__ float g_wxp[FDIM * Z4];
__device__ float g_bp[Z4];
// fp32 state
__device__ float g_h[BATCH * NU];
__device__ float g_c[BATCH * NU];
__device__ __align__(16) float g_pred[BATCH * FDIM];

// ---------------- helpers ----------------
__device__ __forceinline__ void mma16816(float* d, const uint32_t* a,
                                         const uint32_t* b) {
    asm volatile(
        "mma.sync.aligned.m16n8k16.row.col.f32.f16.f16.f32 "
        "{%0,%1,%2,%3}, {%4,%5,%6,%7}, {%8,%9}, {%0,%1,%2,%3};"
        : "+f"(d[0]), "+f"(d[1]), "+f"(d[2]), "+f"(d[3])
        : "r"(a[0]), "r"(a[1]), "r"(a[2]), "r"(a[3]), "r"(b[0]), "r"(b[1]));
}
__device__ __forceinline__ float sigmoid_acc(float x) {
    return 0.5f * (1.0f + tanhf(0.5f * x));
}
__device__ __forceinline__ uint32_t pack_h2(float a, float b) {
    __half2 h = __floats2half2_rn(a, b);
    return *reinterpret_cast<uint32_t*>(&h);
}
// pack hi pair and lo (residual) pair
__device__ __forceinline__ void pack_hilo(float a, float b,
                                          uint32_t& hi, uint32_t& lo) {
    __half2 h = __floats2half2_rn(a, b);
    hi = *reinterpret_cast<uint32_t*>(&h);
    float ra = a - __half2float(__low2half(h));
    float rb = b - __half2float(__high2half(h));
    lo = pack_h2(ra, rb);
}

// ---------------- prep kernels ----------------
// Permuted z-col p: nt=p>>7, loc=p&127; wn=loc>>5, g=(loc>>3)&3, ul=loc&7;
// unit u = nt*32 + wn*8 + ul; original col oc = g*256 + u.
__global__ void prep_b2(const float* __restrict__ Wh) {
    int idx = blockIdx.x * 256 + threadIdx.x;   // 65536 = 128 nt8 x 16 kc x 32
    int lane = idx & 31;
    int kc   = (idx >> 5) & 15;
    int ntile = idx >> 9;
    int q = lane >> 2, s = lane & 3;
    int p = ntile * 8 + q;                      // permuted z-col (n of frag)
    int nt = p >> 7, loc = p & 127;
    int wn = loc >> 5, g = (loc >> 3) & 3, ul = loc & 7;
    int oc = g * 256 + nt * 32 + wn * 8 + ul;   // original Wh column
    int k0 = kc * 16 + 2 * s;
    uint2 r;
    r.x = pack_h2(Wh[(k0    ) * Z4 + oc], Wh[(k0 + 1) * Z4 + oc]);  // b0
    r.y = pack_h2(Wh[(k0 + 8) * Z4 + oc], Wh[(k0 + 9) * Z4 + oc]);  // b1
    g_b2[idx] = r;
}

__global__ void prep_wxb(const float* __restrict__ Wx, const float* __restrict__ b) {
    int p = threadIdx.x;                        // 0..1023
    int nt = p >> 7, loc = p & 127;
    int wn = loc >> 5, g = (loc >> 3) & 3, ul = loc & 7;
    int oc = g * 256 + nt * 32 + wn * 8 + ul;
    g_bp[p] = b[oc];
    #pragma unroll
    for (int f = 0; f < FDIM; f++)
        g_wxp[f * Z4 + p] = Wx[f * Z4 + oc];
}

// ---------------- main timestep kernel ----------------
__global__ void __launch_bounds__(THREADS, 2)
lstm_step_reg(const float* __restrict__ xt, int xstride,
              const uint4* __restrict__ a4h_in,
              const uint4* __restrict__ a4l_in,
              uint4* __restrict__ a4h_out,
              uint4* __restrict__ a4l_out,
              int first)
{
    __shared__ float wx_s[4 * 128];
    __shared__ float bp_s[128];

    const int tid  = threadIdx.x;
    const int lane = tid & 31;
    const int wid  = tid >> 5;
    const int wm   = wid & 1;        // m-warp: rows wm*32..+32 (of 64)
    const int wn   = wid >> 1;       // n-warp: permuted cols wn*32..+32
    const int rt   = blockIdx.x;     // 0..255 (64 rows each)
    const int nt   = blockIdx.y;     // 0..7

    for (int i = tid; i < 4 * 128; i += THREADS) {
        int f = i >> 7, j = i & 127;
        wx_s[i] = g_wxp[f * Z4 + nt * 128 + j];
    }
    if (tid < 128) bp_s[tid] = g_bp[nt * 128 + tid];
    __syncthreads();

    // accumulators d[mi][gate][frag]
    float d[2][4][4];
    #pragma unroll
    for (int mi = 0; mi < 2; mi++)
        #pragma unroll
        for (int g = 0; g < 4; g++)
            #pragma unroll
            for (int r = 0; r < 4; r++)
                d[mi][g][r] = 0.0f;

    if (!first) {
        // A: ((rt*4 + wm*2 + mi)*16 + kc)*32 + lane   (uint4 units)
        // B: ((nt*16 + wn*4 + g)*16 + kc)*32 + lane   (uint2 units)
        const int aBase = ((rt * 4 + wm * 2) * 16) * 32 + lane;
        const int bBase = ((nt * 16 + wn * 4) * 16) * 32 + lane;

        uint4 Ah[2][2], Al[2][2];
        uint2 Bq[2][4];
        #pragma unroll
        for (int mi = 0; mi < 2; mi++) {
            Ah[0][mi] = a4h_in[aBase + mi * 512];
            Al[0][mi] = a4l_in[aBase + mi * 512];
        }
        #pragma unroll
        for (int g = 0; g < 4; g++)
            Bq[0][g] = g_b2[bBase + g * 512];

        #pragma unroll
        for (int kc = 0; kc < NKC; kc++) {
            const int cur = kc & 1, nx = cur ^ 1;
            if (kc < NKC - 1) {
                const int ko = (kc + 1) * 32;
                #pragma unroll
                for (int mi = 0; mi < 2; mi++) {
                    Ah[nx][mi] = a4h_in[aBase + mi * 512 + ko];
                    Al[nx][mi] = a4l_in[aBase + mi * 512 + ko];
                }
                #pragma unroll
                for (int g = 0; g < 4; g++)
                    Bq[nx][g] = g_b2[bBase + g * 512 + ko];
            }
            #pragma unroll
            for (int mi = 0; mi < 2; mi++) {
                const uint32_t* ah = reinterpret_cast<const uint32_t*>(&Ah[cur][mi]);
                const uint32_t* al = reinterpret_cast<const uint32_t*>(&Al[cur][mi]);
                #pragma unroll
                for (int g = 0; g < 4; g++) {
                    const uint32_t bh[2] = {Bq[cur][g].x, Bq[cur][g].y};
                    mma16816(d[mi][g], ah, bh);
                    mma16816(d[mi][g], al, bh);
                }
            }
        }
    }

    // ---- epilogue: z -> gates -> c,h; write fp32 h + A-frag hi/lo ----
    const int q  = lane >> 2;
    const int s4 = lane & 3;
    const int kcs = nt * 2 + (wn >> 1);     // kchunk of this warp's units
    const int slotbase = (wn & 1) * 2;      // a0a1 (k<8) or a2a3 (k>=8)
    uint32_t* ah32 = reinterpret_cast<uint32_t*>(a4h_out);
    uint32_t* al32 = reinterpret_cast<uint32_t*>(a4l_out);

    #pragma unroll
    for (int mi = 0; mi < 2; mi++) {
        float hn[2][2];                      // [rh][par]
        #pragma unroll
        for (int rh = 0; rh < 2; rh++) {
            const int row = rt * 64 + wm * 32 + mi * 16 + q + rh * 8;
            const float4 xv = *reinterpret_cast<const float4*>(
                &xt[(long)row * xstride]);
            const int ci = row * NU + nt * 32 + wn * 8 + s4 * 2;
            float2 cold = first ? make_float2(0.f, 0.f)
                : *reinterpret_cast<const float2*>(&g_c[ci]);
            const float coldv[2] = {cold.x, cold.y};
            float cn2[2], hn2[2];
            #pragma unroll
            for (int par = 0; par < 2; par++) {
                float z[4];
                #pragma unroll
                for (int g = 0; g < 4; g++) {
                    const int nl = wn * 32 + g * 8 + s4 * 2 + par;
                    float zz = bp_s[nl] + d[mi][g][rh * 2 + par];
                    zz = fmaf(xv.x, wx_s[nl],       zz);
                    zz = fmaf(xv.y, wx_s[128 + nl], zz);
                    zz = fmaf(xv.z, wx_s[256 + nl], zz);
                    zz = fmaf(xv.w, wx_s[384 + nl], zz);
                    z[g] = zz;
                }
                const float ig = sigmoid_acc(z[0]);
                const float fg = sigmoid_acc(z[1]);
                const float gg = tanhf(z[2]);
                const float og = sigmoid_acc(z[3]);
                const float cn = fg * coldv[par] + ig * gg;
                const float hv = og * tanhf(cn);
                cn2[par] = cn;
                hn2[par] = hv;
                hn[rh][par] = hv;
            }
            *reinterpret_cast<float2*>(&g_c[ci]) = make_float2(cn2[0], cn2[1]);
            *reinterpret_cast<float2*>(&g_h[ci]) = make_float2(hn2[0], hn2[1]);
        }
        // A-fragment store (identity map): rh=0 -> a0/a2, rh=1 -> a1/a3;
        // wn even -> cols 2s,2s+1 (a0a1), wn odd -> cols 8+2s.. (a2a3).
        const int m16blk = rt * 4 + wm * 2 + mi;
        const int fb = ((m16blk * 16 + kcs) * 32 + lane) * 4 + slotbase;
        uint2 fh, fl;
        pack_hilo(hn[0][0], hn[0][1], fh.x, fl.x);
        pack_hilo(hn[1][0], hn[1][1], fh.y, fl.y);
        *reinterpret_cast<uint2*>(&ah32[fb]) = fh;
        *reinterpret_cast<uint2*>(&al32[fb]) = fl;
    }
}

// pred = h @ Wd + bd ; writes output slice and feedback buffer.
__global__ void pred_kernel(const float* __restrict__ h,
                            const float* __restrict__ Wd,
                            const float* __restrict__ bd,
                            float* __restrict__ out, int ostride,
                            float* __restrict__ pred)
{
    const int gwarp = (blockIdx.x * blockDim.x + threadIdx.x) >> 5;
    const int lane  = threadIdx.x & 31;
    if (gwarp >= BATCH) return;

    const float* hrow = h + gwarp * NU;
    float a0 = 0.f, a1 = 0.f, a2 = 0.f, a3 = 0.f;
    #pragma unroll
    for (int k = lane; k < NU; k += 32) {
        float hv = hrow[k];
        float4 wv = *reinterpret_cast<const float4*>(&Wd[k * 4]);
        a0 = fmaf(hv, wv.x, a0);
        a1 = fmaf(hv, wv.y, a1);
        a2 = fmaf(hv, wv.z, a2);
        a3 = fmaf(hv, wv.w, a3);
    }
    #pragma unroll
    for (int off = 16; off > 0; off >>= 1) {
        a0 += __shfl_down_sync(0xffffffffu, a0, off);
        a1 += __shfl_down_sync(0xffffffffu, a1, off);
        a2 += __shfl_down_sync(0xffffffffu, a2, off);
        a3 += __shfl_down_sync(0xffffffffu, a3, off);
    }
    if (lane == 0) {
        float4 r = make_float4(a0 + bd[0], a1 + bd[1], a2 + bd[2], a3 + bd[3]);
        *reinterpret_cast<float4*>(&out[(long)gwarp * ostride]) = r;
        *reinterpret_cast<float4*>(&pred[gwarp * 4]) = r;
    }
}

extern "C" void kernel_launch(void* const* d_in, const int* in_sizes, int n_in,
                              void* d_out, int out_size)
{
    const float* x  = (const float*)d_in[0];
    const float* Wx = (const float*)d_in[1];
    const float* Wh = (const float*)d_in[2];
    const float* b  = (const float*)d_in[3];
    const float* Wd = (const float*)d_in[4];
    const float* bd = (const float*)d_in[5];
    float* out = (float*)d_out;

    float* pred_ptr = nullptr;
    float* h_ptr = nullptr;
    uint4* ah = nullptr;
    uint4* al = nullptr;
    cudaGetSymbolAddress((void**)&pred_ptr, g_pred);
    cudaGetSymbolAddress((void**)&h_ptr, g_h);
    cudaGetSymbolAddress((void**)&ah, g_a4h);
    cudaGetSymbolAddress((void**)&al, g_a4l);
    const long BUFQ = (long)NM16 * NKC * 32;
    uint4* ahb[2] = {ah, ah + BUFQ};
    uint4* alb[2] = {al, al + BUFQ};

    // weight prep (re-run every replay -> deterministic)
    prep_b2<<<256, 256>>>(Wh);
    prep_wxb<<<1, 1024>>>(Wx, b);

    const dim3 sgrid(256, 8);          // (row tiles, unit tiles) — rt fastest
    const int pblocks = (BATCH * 32) / 256;

    int step = 0;
    lstm_step_reg<<<sgrid, THREADS>>>(x, SEQ_T * FDIM,
        ahb[1], alb[1], ahb[0], alb[0], 1);
    step = 1;
    for (int t = 1; t < SEQ_T; t++, step++)
        lstm_step_reg<<<sgrid, THREADS>>>(x + t * FDIM, SEQ_T * FDIM,
            ahb[(step - 1) & 1], alb[(step - 1) & 1],
            ahb[step & 1], alb[step & 1], 0);

    pred_kernel<<<pblocks, 256>>>(h_ptr, Wd, bd, out, NOUT * FDIM, pred_ptr);

    for (int s = 1; s < NOUT; s++, step++) {
        lstm_step_reg<<<sgrid, THREADS>>>(pred_ptr, FDIM,
            ahb[(step - 1) & 1], alb[(step - 1) & 1],
            ahb[step & 1], alb[step & 1], 0);
        pred_kernel<<<pblocks, 256>>>(h_ptr, Wd, bd, out + s * FDIM,
                                      NOUT * FDIM, pred_ptr);
    }
}

// round 11
// speedup vs baseline: 4.4659x; 1.0934x over previous
#include <cuda_runtime.h>
#include <cuda_fp16.h>
#include <cstdint>

// ---------------------------------------------------------------------------
// FeedBack LSTM via mma.sync fp16 (baseline PTX; sm_103 target, no 'a' feats).
// R11: (1) AR feedback folded into the recurrence: Wh' = Wh + Wd@Wx,
//      b' = b + bd@Wx  ->  pred kernels leave the critical path; all 24
//      predictions computed by ONE pred_all kernel at the end from per-step
//      h slots. (2) MUFU tanh.approx.f32 activations (error absorbed by the
//      contractive recurrence). Register-direct fp16 hi/lo 2-term GEMM,
//      warp tile 32x32, 2 CTAs/SM, A-frags written in mma layout (identity).
// B=16384, T=48, F=4, UNITS=256 (z width 1024), OUT_STEPS=24.
// ---------------------------------------------------------------------------

namespace {
constexpr int BATCH = 16384;
constexpr int SEQ_T = 48;
constexpr int FDIM  = 4;
constexpr int NU    = 256;
constexpr int NOUT  = 24;
constexpr int Z4    = 1024;

constexpr int THREADS = 256;   // 8 warps: 2 m-warps x 4 n-warps (warp 32x32)
constexpr int NM16 = BATCH / 16;        // 1024 m16 blocks
constexpr int NKC  = NU / 16;           // 16 k16 chunks
constexpr int NT8  = Z4 / 8;            // 128 n8 tiles
}

// ---------------- device state (allocation-free) ----------------
// A fragments (fp16): [buf][m16blk(1024)][kchunk(16)][lane(32)] : uint4=a0..a3
__device__ __align__(16) uint4 g_a4h[2 * NM16 * NKC * 32];
__device__ __align__(16) uint4 g_a4l[2 * NM16 * NKC * 32];
// B fragments (fp16 hi only): [ntile(128)][kchunk(16)][lane(32)] : uint2=b0,b1
__device__ __align__(16) uint2 g_b2w[NT8 * NKC * 32];    // warmup: Wh
__device__ __align__(16) uint2 g_b2ar[NT8 * NKC * 32];   // AR: Wh + Wd@Wx
// permuted Wx / biases (fp32)
__device__ float g_wxp[FDIM * Z4];
__device__ float g_bp[Z4];       // permuted b
__device__ float g_bpar[Z4];     // permuted b + bd@Wx
// fp32 state
__device__ float g_c[BATCH * NU];
// per-output-step h slots (slot 0 = warmup final; slot s = AR step s)
__device__ float g_hall[NOUT * BATCH * NU];

// ---------------- helpers ----------------
__device__ __forceinline__ void mma16816(float* d, const uint32_t* a,
                                         const uint32_t* b) {
    asm volatile(
        "mma.sync.aligned.m16n8k16.row.col.f32.f16.f16.f32 "
        "{%0,%1,%2,%3}, {%4,%5,%6,%7}, {%8,%9}, {%0,%1,%2,%3};"
        : "+f"(d[0]), "+f"(d[1]), "+f"(d[2]), "+f"(d[3])
        : "r"(a[0]), "r"(a[1]), "r"(a[2]), "r"(a[3]), "r"(b[0]), "r"(b[1]));
}
__device__ __forceinline__ float tanh_fast(float x) {
    float y;
    asm("tanh.approx.f32 %0, %1;" : "=f"(y) : "f"(x));
    return y;
}
__device__ __forceinline__ float sigmoid_fast(float x) {
    return fmaf(0.5f, tanh_fast(0.5f * x), 0.5f);
}
__device__ __forceinline__ uint32_t pack_h2(float a, float b) {
    __half2 h = __floats2half2_rn(a, b);
    return *reinterpret_cast<uint32_t*>(&h);
}
__device__ __forceinline__ void pack_hilo(float a, float b,
                                          uint32_t& hi, uint32_t& lo) {
    __half2 h = __floats2half2_rn(a, b);
    hi = *reinterpret_cast<uint32_t*>(&h);
    float ra = a - __half2float(__low2half(h));
    float rb = b - __half2float(__high2half(h));
    lo = pack_h2(ra, rb);
}

// ---------------- prep kernels ----------------
// Permuted z-col p: nt=p>>7, loc=p&127; wn=loc>>5, g=(loc>>3)&3, ul=loc&7;
// unit u = nt*32 + wn*8 + ul; original col oc = g*256 + u.
// ar=0: W = Wh ; ar=1: W = Wh + Wd@Wx (feedback folded).
__global__ void prep_b2(const float* __restrict__ Wh,
                        const float* __restrict__ Wd,
                        const float* __restrict__ Wx,
                        int ar, uint2* __restrict__ dst) {
    int idx = blockIdx.x * 256 + threadIdx.x;   // 65536 = 128 nt8 x 16 kc x 32
    int lane = idx & 31;
    int kc   = (idx >> 5) & 15;
    int ntile = idx >> 9;
    int q = lane >> 2, s = lane & 3;
    int p = ntile * 8 + q;                      // permuted z-col (n of frag)
    int nt = p >> 7, loc = p & 127;
    int wn = loc >> 5, g = (loc >> 3) & 3, ul = loc & 7;
    int oc = g * 256 + nt * 32 + wn * 8 + ul;   // original z column
    int k0 = kc * 16 + 2 * s;
    float v[4];
    const int kk[4] = {k0, k0 + 1, k0 + 8, k0 + 9};
    #pragma unroll
    for (int j = 0; j < 4; j++) {
        float w = Wh[kk[j] * Z4 + oc];
        if (ar) {
            #pragma unroll
            for (int f = 0; f < FDIM; f++)
                w = fmaf(Wd[kk[j] * FDIM + f], Wx[f * Z4 + oc], w);
        }
        v[j] = w;
    }
    uint2 r;
    r.x = pack_h2(v[0], v[1]);  // b0
    r.y = pack_h2(v[2], v[3]);  // b1
    dst[idx] = r;
}

__global__ void prep_wxb(const float* __restrict__ Wx,
                         const float* __restrict__ b,
                         const float* __restrict__ bd) {
    int p = threadIdx.x;                        // 0..1023
    int nt = p >> 7, loc = p & 127;
    int wn = loc >> 5, g = (loc >> 3) & 3, ul = loc & 7;
    int oc = g * 256 + nt * 32 + wn * 8 + ul;
    float bb = b[oc];
    g_bp[p] = bb;
    float ba = bb;
    #pragma unroll
    for (int f = 0; f < FDIM; f++) {
        g_wxp[f * Z4 + p] = Wx[f * Z4 + oc];
        ba = fmaf(bd[f], Wx[f * Z4 + oc], ba);
    }
    g_bpar[p] = ba;
}

// ---------------- main timestep kernel ----------------
__global__ void __launch_bounds__(THREADS, 2)
lstm_step_reg(const float* __restrict__ xt, int xstride, int has_x,
              const float* __restrict__ bias,
              const uint2* __restrict__ b2,
              const uint4* __restrict__ a4h_in,
              const uint4* __restrict__ a4l_in,
              uint4* __restrict__ a4h_out,
              uint4* __restrict__ a4l_out,
              float* __restrict__ h_slot,
              int first)
{
    __shared__ float wx_s[4 * 128];
    __shared__ float bp_s[128];

    const int tid  = threadIdx.x;
    const int lane = tid & 31;
    const int wid  = tid >> 5;
    const int wm   = wid & 1;        // m-warp: rows wm*32..+32 (of 64)
    const int wn   = wid >> 1;       // n-warp: permuted cols wn*32..+32
    const int rt   = blockIdx.x;     // 0..255 (64 rows each)
    const int nt   = blockIdx.y;     // 0..7

    for (int i = tid; i < 4 * 128; i += THREADS) {
        int f = i >> 7, j = i & 127;
        wx_s[i] = g_wxp[f * Z4 + nt * 128 + j];
    }
    if (tid < 128) bp_s[tid] = bias[nt * 128 + tid];
    __syncthreads();

    // accumulators d[mi][gate][frag]
    float d[2][4][4];
    #pragma unroll
    for (int mi = 0; mi < 2; mi++)
        #pragma unroll
        for (int g = 0; g < 4; g++)
            #pragma unroll
            for (int r = 0; r < 4; r++)
                d[mi][g][r] = 0.0f;

    if (!first) {
        // A: ((rt*4 + wm*2 + mi)*16 + kc)*32 + lane   (uint4 units)
        // B: ((nt*16 + wn*4 + g)*16 + kc)*32 + lane   (uint2 units)
        const int aBase = ((rt * 4 + wm * 2) * 16) * 32 + lane;
        const int bBase = ((nt * 16 + wn * 4) * 16) * 32 + lane;

        uint4 Ah[2][2], Al[2][2];
        uint2 Bq[2][4];
        #pragma unroll
        for (int mi = 0; mi < 2; mi++) {
            Ah[0][mi] = a4h_in[aBase + mi * 512];
            Al[0][mi] = a4l_in[aBase + mi * 512];
        }
        #pragma unroll
        for (int g = 0; g < 4; g++)
            Bq[0][g] = b2[bBase + g * 512];

        #pragma unroll
        for (int kc = 0; kc < NKC; kc++) {
            const int cur = kc & 1, nx = cur ^ 1;
            if (kc < NKC - 1) {
                const int ko = (kc + 1) * 32;
                #pragma unroll
                for (int mi = 0; mi < 2; mi++) {
                    Ah[nx][mi] = a4h_in[aBase + mi * 512 + ko];
                    Al[nx][mi] = a4l_in[aBase + mi * 512 + ko];
                }
                #pragma unroll
                for (int g = 0; g < 4; g++)
                    Bq[nx][g] = b2[bBase + g * 512 + ko];
            }
            #pragma unroll
            for (int mi = 0; mi < 2; mi++) {
                const uint32_t* ah = reinterpret_cast<const uint32_t*>(&Ah[cur][mi]);
                const uint32_t* al = reinterpret_cast<const uint32_t*>(&Al[cur][mi]);
                #pragma unroll
                for (int g = 0; g < 4; g++) {
                    const uint32_t bh[2] = {Bq[cur][g].x, Bq[cur][g].y};
                    mma16816(d[mi][g], ah, bh);
                    mma16816(d[mi][g], al, bh);
                }
            }
        }
    }

    // ---- epilogue: z -> gates -> c,h; write fp32 h + A-frag hi/lo ----
    const int q  = lane >> 2;
    const int s4 = lane & 3;
    const int kcs = nt * 2 + (wn >> 1);     // kchunk of this warp's units
    const int slotbase = (wn & 1) * 2;      // a0a1 (k<8) or a2a3 (k>=8)
    uint32_t* ah32 = reinterpret_cast<uint32_t*>(a4h_out);
    uint32_t* al32 = reinterpret_cast<uint32_t*>(a4l_out);

    #pragma unroll
    for (int mi = 0; mi < 2; mi++) {
        float hn[2][2];                      // [rh][par]
        #pragma unroll
        for (int rh = 0; rh < 2; rh++) {
            const int row = rt * 64 + wm * 32 + mi * 16 + q + rh * 8;
            float4 xv = make_float4(0.f, 0.f, 0.f, 0.f);
            if (has_x)
                xv = *reinterpret_cast<const float4*>(&xt[(long)row * xstride]);
            const int ci = row * NU + nt * 32 + wn * 8 + s4 * 2;
            float2 cold = first ? make_float2(0.f, 0.f)
                : *reinterpret_cast<const float2*>(&g_c[ci]);
            const float coldv[2] = {cold.x, cold.y};
            float cn2[2], hn2[2];
            #pragma unroll
            for (int par = 0; par < 2; par++) {
                float z[4];
                #pragma unroll
                for (int g = 0; g < 4; g++) {
                    const int nl = wn * 32 + g * 8 + s4 * 2 + par;
                    float zz = bp_s[nl] + d[mi][g][rh * 2 + par];
                    if (has_x) {
                        zz = fmaf(xv.x, wx_s[nl],       zz);
                        zz = fmaf(xv.y, wx_s[128 + nl], zz);
                        zz = fmaf(xv.z, wx_s[256 + nl], zz);
                        zz = fmaf(xv.w, wx_s[384 + nl], zz);
                    }
                    z[g] = zz;
                }
                const float ig = sigmoid_fast(z[0]);
                const float fg = sigmoid_fast(z[1]);
                const float gg = tanh_fast(z[2]);
                const float og = sigmoid_fast(z[3]);
                const float cn = fg * coldv[par] + ig * gg;
                const float hv = og * tanh_fast(cn);
                cn2[par] = cn;
                hn2[par] = hv;
                hn[rh][par] = hv;
            }
            *reinterpret_cast<float2*>(&g_c[ci]) = make_float2(cn2[0], cn2[1]);
            *reinterpret_cast<float2*>(&h_slot[ci]) = make_float2(hn2[0], hn2[1]);
        }
        // A-fragment store (identity map)
        const int m16blk = rt * 4 + wm * 2 + mi;
        const int fb = ((m16blk * 16 + kcs) * 32 + lane) * 4 + slotbase;
        uint2 fh, fl;
        pack_hilo(hn[0][0], hn[0][1], fh.x, fl.x);
        pack_hilo(hn[1][0], hn[1][1], fh.y, fl.y);
        *reinterpret_cast<uint2*>(&ah32[fb]) = fh;
        *reinterpret_cast<uint2*>(&al32[fb]) = fl;
    }
}

// All 24 predictions in one launch: out[row, s, :] = hall[s, row, :]@Wd + bd
__global__ void pred_all(const float* __restrict__ hall,
                         const float* __restrict__ Wd,
                         const float* __restrict__ bd,
                         float* __restrict__ out)
{
    const int gwarp = (blockIdx.x * blockDim.x + threadIdx.x) >> 5;
    const int lane  = threadIdx.x & 31;
    if (gwarp >= NOUT * BATCH) return;
    const int s   = gwarp >> 14;          // / BATCH
    const int row = gwarp & (BATCH - 1);

    const float* hrow = hall + ((long)s * BATCH + row) * NU;
    float a0 = 0.f, a1 = 0.f, a2 = 0.f, a3 = 0.f;
    #pragma unroll
    for (int k = lane; k < NU; k += 32) {
        float hv = hrow[k];
        float4 wv = *reinterpret_cast<const float4*>(&Wd[k * 4]);
        a0 = fmaf(hv, wv.x, a0);
        a1 = fmaf(hv, wv.y, a1);
        a2 = fmaf(hv, wv.z, a2);
        a3 = fmaf(hv, wv.w, a3);
    }
    #pragma unroll
    for (int off = 16; off > 0; off >>= 1) {
        a0 += __shfl_down_sync(0xffffffffu, a0, off);
        a1 += __shfl_down_sync(0xffffffffu, a1, off);
        a2 += __shfl_down_sync(0xffffffffu, a2, off);
        a3 += __shfl_down_sync(0xffffffffu, a3, off);
    }
    if (lane == 0) {
        float4 r = make_float4(a0 + bd[0], a1 + bd[1], a2 + bd[2], a3 + bd[3]);
        *reinterpret_cast<float4*>(&out[((long)row * NOUT + s) * FDIM]) = r;
    }
}

extern "C" void kernel_launch(void* const* d_in, const int* in_sizes, int n_in,
                              void* d_out, int out_size)
{
    const float* x  = (const float*)d_in[0];
    const float* Wx = (const float*)d_in[1];
    const float* Wh = (const float*)d_in[2];
    const float* b  = (const float*)d_in[3];
    const float* Wd = (const float*)d_in[4];
    const float* bd = (const float*)d_in[5];
    float* out = (float*)d_out;

    uint4 *ah = nullptr, *al = nullptr;
    uint2 *b2w = nullptr, *b2ar = nullptr;
    float *bp = nullptr, *bpar = nullptr, *hall = nullptr;
    cudaGetSymbolAddress((void**)&ah, g_a4h);
    cudaGetSymbolAddress((void**)&al, g_a4l);
    cudaGetSymbolAddress((void**)&b2w, g_b2w);
    cudaGetSymbolAddress((void**)&b2ar, g_b2ar);
    cudaGetSymbolAddress((void**)&bp, g_bp);
    cudaGetSymbolAddress((void**)&bpar, g_bpar);
    cudaGetSymbolAddress((void**)&hall, g_hall);
    const long BUFQ = (long)NM16 * NKC * 32;
    uint4* ahb[2] = {ah, ah + BUFQ};
    uint4* alb[2] = {al, al + BUFQ};
    const long HSLOT = (long)BATCH * NU;

    // weight prep (re-run every replay -> deterministic)
    prep_b2<<<256, 256>>>(Wh, Wd, Wx, 0, b2w);
    prep_b2<<<256, 256>>>(Wh, Wd, Wx, 1, b2ar);
    prep_wxb<<<1, 1024>>>(Wx, b, bd);

    const dim3 sgrid(256, 8);          // (row tiles, unit tiles) — rt fastest

    int step = 0;
    // warmup: h written to slot 0 each step (only final one matters)
    lstm_step_reg<<<sgrid, THREADS>>>(x, SEQ_T * FDIM, 1, bp, b2w,
        ahb[1], alb[1], ahb[0], alb[0], hall, 1);
    step = 1;
    for (int t = 1; t < SEQ_T; t++, step++)
        lstm_step_reg<<<sgrid, THREADS>>>(x + t * FDIM, SEQ_T * FDIM, 1, bp, b2w,
            ahb[(step - 1) & 1], alb[(step - 1) & 1],
            ahb[step & 1], alb[step & 1], hall, 0);

    // AR steps: folded weights, no x; h_s -> slot s
    for (int s = 1; s < NOUT; s++, step++)
        lstm_step_reg<<<sgrid, THREADS>>>(nullptr, 0, 0, bpar, b2ar,
            ahb[(step - 1) & 1], alb[(step - 1) & 1],
            ahb[step & 1], alb[step & 1], hall + (long)s * HSLOT, 0);

    // all predictions in one shot
    const int pblocks = (NOUT * BATCH * 32) / 256;
    pred_all<<<pblocks, 256>>>(hall, Wd, bd, out);
}

// round 12
// speedup vs baseline: 6.0051x; 1.3447x over previous
#include <cuda_runtime.h>
#include <cuda_fp16.h>
#include <cstdint>

// ---------------------------------------------------------------------------
// FeedBack LSTM via mma.sync fp16 (baseline PTX; sm_103 target, no 'a' feats).
// R12: single-term fp16 GEMM (z = Ah·Bh; A and B both fp16-rounded, per-step
// error ~2^-11 absorbed by the contractive recurrence — calibrated from
// R10/R11). Register-direct, no barriers in K-loop, folded AR weights
// (Wh' = Wh + Wd@Wx), one pred_all at the end, MUFU activations.
// h fp32 stored ONLY on steps whose h feeds an output (47..71).
// B=16384, T=48, F=4, UNITS=256 (z width 1024), OUT_STEPS=24.
// ---------------------------------------------------------------------------

namespace {
constexpr int BATCH = 16384;
constexpr int SEQ_T = 48;
constexpr int FDIM  = 4;
constexpr int NU    = 256;
constexpr int NOUT  = 24;
constexpr int Z4    = 1024;

constexpr int THREADS = 256;   // 8 warps: 2 m-warps x 4 n-warps (warp 32x32)
constexpr int NM16 = BATCH / 16;        // 1024 m16 blocks
constexpr int NKC  = NU / 16;           // 16 k16 chunks
constexpr int NT8  = Z4 / 8;            // 128 n8 tiles
}

// ---------------- device state (allocation-free) ----------------
// A fragments (fp16 hi): [buf][m16blk(1024)][kchunk(16)][lane(32)] : uint4
__device__ __align__(16) uint4 g_a4h[2 * NM16 * NKC * 32];
// B fragments (fp16): [ntile(128)][kchunk(16)][lane(32)] : uint2 = b0,b1
__device__ __align__(16) uint2 g_b2w[NT8 * NKC * 32];    // warmup: Wh
__device__ __align__(16) uint2 g_b2ar[NT8 * NKC * 32];   // AR: Wh + Wd@Wx
// permuted Wx / biases (fp32)
__device__ float g_wxp[FDIM * Z4];
__device__ float g_bp[Z4];       // permuted b
__device__ float g_bpar[Z4];     // permuted b + bd@Wx
// fp32 state
__device__ float g_c[BATCH * NU];
// per-output-step h slots (slot 0 = warmup final; slot s = AR step s)
__device__ float g_hall[NOUT * BATCH * NU];

// ---------------- helpers ----------------
__device__ __forceinline__ void mma16816(float* d, const uint32_t* a,
                                         const uint32_t* b) {
    asm volatile(
        "mma.sync.aligned.m16n8k16.row.col.f32.f16.f16.f32 "
        "{%0,%1,%2,%3}, {%4,%5,%6,%7}, {%8,%9}, {%0,%1,%2,%3};"
        : "+f"(d[0]), "+f"(d[1]), "+f"(d[2]), "+f"(d[3])
        : "r"(a[0]), "r"(a[1]), "r"(a[2]), "r"(a[3]), "r"(b[0]), "r"(b[1]));
}
__device__ __forceinline__ float tanh_fast(float x) {
    float y;
    asm("tanh.approx.f32 %0, %1;" : "=f"(y) : "f"(x));
    return y;
}
__device__ __forceinline__ float sigmoid_fast(float x) {
    return fmaf(0.5f, tanh_fast(0.5f * x), 0.5f);
}
__device__ __forceinline__ uint32_t pack_h2(float a, float b) {
    __half2 h = __floats2half2_rn(a, b);
    return *reinterpret_cast<uint32_t*>(&h);
}

// ---------------- prep kernels ----------------
// Permuted z-col p: nt=p>>7, loc=p&127; wn=loc>>5, g=(loc>>3)&3, ul=loc&7;
// unit u = nt*32 + wn*8 + ul; original col oc = g*256 + u.
// ar=0: W = Wh ; ar=1: W = Wh + Wd@Wx (feedback folded).
__global__ void prep_b2(const float* __restrict__ Wh,
                        const float* __restrict__ Wd,
                        const float* __restrict__ Wx,
                        int ar, uint2* __restrict__ dst) {
    int idx = blockIdx.x * 256 + threadIdx.x;   // 65536 = 128 nt8 x 16 kc x 32
    int lane = idx & 31;
    int kc   = (idx >> 5) & 15;
    int ntile = idx >> 9;
    int q = lane >> 2, s = lane & 3;
    int p = ntile * 8 + q;                      // permuted z-col (n of frag)
    int nt = p >> 7, loc = p & 127;
    int wn = loc >> 5, g = (loc >> 3) & 3, ul = loc & 7;
    int oc = g * 256 + nt * 32 + wn * 8 + ul;   // original z column
    int k0 = kc * 16 + 2 * s;
    float v[4];
    const int kk[4] = {k0, k0 + 1, k0 + 8, k0 + 9};
    #pragma unroll
    for (int j = 0; j < 4; j++) {
        float w = Wh[kk[j] * Z4 + oc];
        if (ar) {
            #pragma unroll
            for (int f = 0; f < FDIM; f++)
                w = fmaf(Wd[kk[j] * FDIM + f], Wx[f * Z4 + oc], w);
        }
        v[j] = w;
    }
    uint2 r;
    r.x = pack_h2(v[0], v[1]);  // b0
    r.y = pack_h2(v[2], v[3]);  // b1
    dst[idx] = r;
}

__global__ void prep_wxb(const float* __restrict__ Wx,
                         const float* __restrict__ b,
                         const float* __restrict__ bd) {
    int p = threadIdx.x;                        // 0..1023
    int nt = p >> 7, loc = p & 127;
    int wn = loc >> 5, g = (loc >> 3) & 3, ul = loc & 7;
    int oc = g * 256 + nt * 32 + wn * 8 + ul;
    float bb = b[oc];
    g_bp[p] = bb;
    float ba = bb;
    #pragma unroll
    for (int f = 0; f < FDIM; f++) {
        g_wxp[f * Z4 + p] = Wx[f * Z4 + oc];
        ba = fmaf(bd[f], Wx[f * Z4 + oc], ba);
    }
    g_bpar[p] = ba;
}

// ---------------- main timestep kernel ----------------
__global__ void __launch_bounds__(THREADS, 2)
lstm_step_reg(const float* __restrict__ xt, int xstride, int has_x,
              const float* __restrict__ bias,
              const uint2* __restrict__ b2,
              const uint4* __restrict__ a4h_in,
              uint4* __restrict__ a4h_out,
              float* __restrict__ h_slot,     // may be nullptr
              int first)
{
    __shared__ float wx_s[4 * 128];
    __shared__ float bp_s[128];

    const int tid  = threadIdx.x;
    const int lane = tid & 31;
    const int wid  = tid >> 5;
    const int wm   = wid & 1;        // m-warp: rows wm*32..+32 (of 64)
    const int wn   = wid >> 1;       // n-warp: permuted cols wn*32..+32
    const int rt   = blockIdx.x;     // 0..255 (64 rows each)
    const int nt   = blockIdx.y;     // 0..7

    for (int i = tid; i < 4 * 128; i += THREADS) {
        int f = i >> 7, j = i & 127;
        wx_s[i] = g_wxp[f * Z4 + nt * 128 + j];
    }
    if (tid < 128) bp_s[tid] = bias[nt * 128 + tid];
    __syncthreads();

    // accumulators d[mi][gate][frag]
    float d[2][4][4];
    #pragma unroll
    for (int mi = 0; mi < 2; mi++)
        #pragma unroll
        for (int g = 0; g < 4; g++)
            #pragma unroll
            for (int r = 0; r < 4; r++)
                d[mi][g][r] = 0.0f;

    if (!first) {
        // A: ((rt*4 + wm*2 + mi)*16 + kc)*32 + lane   (uint4 units)
        // B: ((nt*16 + wn*4 + g)*16 + kc)*32 + lane   (uint2 units)
        const int aBase = ((rt * 4 + wm * 2) * 16) * 32 + lane;
        const int bBase = ((nt * 16 + wn * 4) * 16) * 32 + lane;

        uint4 Ah[2][2];
        uint2 Bq[2][4];
        #pragma unroll
        for (int mi = 0; mi < 2; mi++)
            Ah[0][mi] = a4h_in[aBase + mi * 512];
        #pragma unroll
        for (int g = 0; g < 4; g++)
            Bq[0][g] = b2[bBase + g * 512];

        #pragma unroll
        for (int kc = 0; kc < NKC; kc++) {
            const int cur = kc & 1, nx = cur ^ 1;
            if (kc < NKC - 1) {
                const int ko = (kc + 1) * 32;
                #pragma unroll
                for (int mi = 0; mi < 2; mi++)
                    Ah[nx][mi] = a4h_in[aBase + mi * 512 + ko];
                #pragma unroll
                for (int g = 0; g < 4; g++)
                    Bq[nx][g] = b2[bBase + g * 512 + ko];
            }
            #pragma unroll
            for (int mi = 0; mi < 2; mi++) {
                const uint32_t* ah = reinterpret_cast<const uint32_t*>(&Ah[cur][mi]);
                #pragma unroll
                for (int g = 0; g < 4; g++) {
                    const uint32_t bh[2] = {Bq[cur][g].x, Bq[cur][g].y};
                    mma16816(d[mi][g], ah, bh);
                }
            }
        }
    }

    // ---- epilogue: z -> gates -> c,h; write A-frag (+ fp32 h if needed) ----
    const int q  = lane >> 2;
    const int s4 = lane & 3;
    const int kcs = nt * 2 + (wn >> 1);     // kchunk of this warp's units
    const int slotbase = (wn & 1) * 2;      // a0a1 (k<8) or a2a3 (k>=8)
    uint32_t* ah32 = reinterpret_cast<uint32_t*>(a4h_out);

    #pragma unroll
    for (int mi = 0; mi < 2; mi++) {
        float hn[2][2];                      // [rh][par]
        #pragma unroll
        for (int rh = 0; rh < 2; rh++) {
            const int row = rt * 64 + wm * 32 + mi * 16 + q + rh * 8;
            float4 xv = make_float4(0.f, 0.f, 0.f, 0.f);
            if (has_x)
                xv = *reinterpret_cast<const float4*>(&xt[(long)row * xstride]);
            const int ci = row * NU + nt * 32 + wn * 8 + s4 * 2;
            float2 cold = first ? make_float2(0.f, 0.f)
                : *reinterpret_cast<const float2*>(&g_c[ci]);
            const float coldv[2] = {cold.x, cold.y};
            float cn2[2], hn2[2];
            #pragma unroll
            for (int par = 0; par < 2; par++) {
                float z[4];
                #pragma unroll
                for (int g = 0; g < 4; g++) {
                    const int nl = wn * 32 + g * 8 + s4 * 2 + par;
                    float zz = bp_s[nl] + d[mi][g][rh * 2 + par];
                    if (has_x) {
                        zz = fmaf(xv.x, wx_s[nl],       zz);
                        zz = fmaf(xv.y, wx_s[128 + nl], zz);
                        zz = fmaf(xv.z, wx_s[256 + nl], zz);
                        zz = fmaf(xv.w, wx_s[384 + nl], zz);
                    }
                    z[g] = zz;
                }
                const float ig = sigmoid_fast(z[0]);
                const float fg = sigmoid_fast(z[1]);
                const float gg = tanh_fast(z[2]);
                const float og = sigmoid_fast(z[3]);
                const float cn = fg * coldv[par] + ig * gg;
                const float hv = og * tanh_fast(cn);
                cn2[par] = cn;
                hn2[par] = hv;
                hn[rh][par] = hv;
            }
            *reinterpret_cast<float2*>(&g_c[ci]) = make_float2(cn2[0], cn2[1]);
            if (h_slot)
                *reinterpret_cast<float2*>(&h_slot[ci]) =
                    make_float2(hn2[0], hn2[1]);
        }
        // A-fragment store (identity map): rh=0 -> a0/a2, rh=1 -> a1/a3;
        // wn even -> cols 2s,2s+1 (a0a1), wn odd -> cols 8+2s.. (a2a3).
        const int m16blk = rt * 4 + wm * 2 + mi;
        const int fb = ((m16blk * 16 + kcs) * 32 + lane) * 4 + slotbase;
        uint2 fh;
        fh.x = pack_h2(hn[0][0], hn[0][1]);
        fh.y = pack_h2(hn[1][0], hn[1][1]);
        *reinterpret_cast<uint2*>(&ah32[fb]) = fh;
    }
}

// All 24 predictions in one launch: out[row, s, :] = hall[s, row, :]@Wd + bd
__global__ void pred_all(const float* __restrict__ hall,
                         const float* __restrict__ Wd,
                         const float* __restrict__ bd,
                         float* __restrict__ out)
{
    const int gwarp = (blockIdx.x * blockDim.x + threadIdx.x) >> 5;
    const int lane  = threadIdx.x & 31;
    if (gwarp >= NOUT * BATCH) return;
    const int s   = gwarp >> 14;          // / BATCH
    const int row = gwarp & (BATCH - 1);

    const float* hrow = hall + ((long)s * BATCH + row) * NU;
    float a0 = 0.f, a1 = 0.f, a2 = 0.f, a3 = 0.f;
    #pragma unroll
    for (int k = lane; k < NU; k += 32) {
        float hv = hrow[k];
        float4 wv = *reinterpret_cast<const float4*>(&Wd[k * 4]);
        a0 = fmaf(hv, wv.x, a0);
        a1 = fmaf(hv, wv.y, a1);
        a2 = fmaf(hv, wv.z, a2);
        a3 = fmaf(hv, wv.w, a3);
    }
    #pragma unroll
    for (int off = 16; off > 0; off >>= 1) {
        a0 += __shfl_down_sync(0xffffffffu, a0, off);
        a1 += __shfl_down_sync(0xffffffffu, a1, off);
        a2 += __shfl_down_sync(0xffffffffu, a2, off);
        a3 += __shfl_down_sync(0xffffffffu, a3, off);
    }
    if (lane == 0) {
        float4 r = make_float4(a0 + bd[0], a1 + bd[1], a2 + bd[2], a3 + bd[3]);
        *reinterpret_cast<float4*>(&out[((long)row * NOUT + s) * FDIM]) = r;
    }
}

extern "C" void kernel_launch(void* const* d_in, const int* in_sizes, int n_in,
                              void* d_out, int out_size)
{
    const float* x  = (const float*)d_in[0];
    const float* Wx = (const float*)d_in[1];
    const float* Wh = (const float*)d_in[2];
    const float* b  = (const float*)d_in[3];
    const float* Wd = (const float*)d_in[4];
    const float* bd = (const float*)d_in[5];
    float* out = (float*)d_out;

    uint4* ah = nullptr;
    uint2 *b2w = nullptr, *b2ar = nullptr;
    float *bp = nullptr, *bpar = nullptr, *hall = nullptr;
    cudaGetSymbolAddress((void**)&ah, g_a4h);
    cudaGetSymbolAddress((void**)&b2w, g_b2w);
    cudaGetSymbolAddress((void**)&b2ar, g_b2ar);
    cudaGetSymbolAddress((void**)&bp, g_bp);
    cudaGetSymbolAddress((void**)&bpar, g_bpar);
    cudaGetSymbolAddress((void**)&hall, g_hall);
    const long BUFQ = (long)NM16 * NKC * 32;
    uint4* ahb[2] = {ah, ah + BUFQ};
    const long HSLOT = (long)BATCH * NU;

    // weight prep (re-run every replay -> deterministic)
    prep_b2<<<256, 256>>>(Wh, Wd, Wx, 0, b2w);
    prep_b2<<<256, 256>>>(Wh, Wd, Wx, 1, b2ar);
    prep_wxb<<<1, 1024>>>(Wx, b, bd);

    const dim3 sgrid(256, 8);          // (row tiles, unit tiles) — rt fastest

    int step = 0;
    // warmup steps 0..46: h fp32 not needed (only A-frags carry state)
    lstm_step_reg<<<sgrid, THREADS>>>(x, SEQ_T * FDIM, 1, bp, b2w,
        ahb[1], ahb[0], nullptr, 1);
    step = 1;
    for (int t = 1; t < SEQ_T - 1; t++, step++)
        lstm_step_reg<<<sgrid, THREADS>>>(x + t * FDIM, SEQ_T * FDIM, 1, bp, b2w,
            ahb[(step - 1) & 1], ahb[step & 1], nullptr, 0);
    // warmup step 47: h -> slot 0 (feeds pred0)
    lstm_step_reg<<<sgrid, THREADS>>>(x + (SEQ_T - 1) * FDIM, SEQ_T * FDIM, 1,
        bp, b2w, ahb[(step - 1) & 1], ahb[step & 1], hall, 0);
    step++;

    // AR steps: folded weights, no x; h_s -> slot s
    for (int s = 1; s < NOUT; s++, step++)
        lstm_step_reg<<<sgrid, THREADS>>>(nullptr, 0, 0, bpar, b2ar,
            ahb[(step - 1) & 1], ahb[step & 1], hall + (long)s * HSLOT, 0);

    // all predictions in one shot
    const int pblocks = (NOUT * BATCH * 32) / 256;
    pred_all<<<pblocks, 256>>>(hall, Wd, bd, out);
}

// round 13
// speedup vs baseline: 6.2449x; 1.0399x over previous
#include <cuda_runtime.h>
#include <cuda_fp16.h>
#include <cstdint>

// ---------------------------------------------------------------------------
// FeedBack LSTM via mma.sync fp16 (baseline PTX; sm_103 target, no 'a' feats).
// R13: ONE persistent kernel for all 71 recurrent steps. 256 co-resident CTAs
// (8 tiles each, fixed nt), software grid barrier between steps (fence/arrive/
// spin/fence). A-fragment loads use __ldcg (L1 not flushed inside a launch;
// frags are written by other SMs). Single-term fp16 GEMM (R12 math, bit-
// identical): z = Ah·Bh, folded AR weights, MUFU activations, one pred_all.
// B=16384, T=48, F=4, UNITS=256 (z width 1024), OUT_STEPS=24.
// ---------------------------------------------------------------------------

namespace {
constexpr int BATCH = 16384;
constexpr int SEQ_T = 48;
constexpr int FDIM  = 4;
constexpr int NU    = 256;
constexpr int NOUT  = 24;
constexpr int Z4    = 1024;

constexpr int THREADS = 256;   // 8 warps: 2 m-warps x 4 n-warps (warp 32x32)
constexpr int NM16 = BATCH / 16;        // 1024 m16 blocks
constexpr int NKC  = NU / 16;           // 16 k16 chunks
constexpr int NT8  = Z4 / 8;            // 128 n8 tiles
constexpr int NCTA = 256;               // persistent grid (<=296 capacity)
constexpr int NSTEPS = SEQ_T + NOUT - 1;  // 71
constexpr long BUFQ = (long)NM16 * NKC * 32;
constexpr long HSLOT = (long)BATCH * NU;
}

// ---------------- device state (allocation-free) ----------------
// A fragments (fp16 hi): [buf][m16blk(1024)][kchunk(16)][lane(32)] : uint4
__device__ __align__(16) uint4 g_a4h[2 * NM16 * NKC * 32];
// B fragments (fp16): [ntile(128)][kchunk(16)][lane(32)] : uint2 = b0,b1
__device__ __align__(16) uint2 g_b2w[NT8 * NKC * 32];    // warmup: Wh
__device__ __align__(16) uint2 g_b2ar[NT8 * NKC * 32];   // AR: Wh + Wd@Wx
// permuted Wx / biases (fp32)
__device__ float g_wxp[FDIM * Z4];
__device__ float g_bp[Z4];       // permuted b
__device__ float g_bpar[Z4];     // permuted b + bd@Wx
// fp32 state
__device__ float g_c[BATCH * NU];
// per-output-step h slots (slot 0 = warmup final; slot s = AR step s)
__device__ float g_hall[NOUT * BATCH * NU];
// grid barrier state (gen monotonic across replays; count self-resets)
__device__ volatile unsigned int g_bar_gen;
__device__ unsigned int g_bar_count;

// ---------------- helpers ----------------
__device__ __forceinline__ void mma16816(float* d, const uint32_t* a,
                                         const uint32_t* b) {
    asm volatile(
        "mma.sync.aligned.m16n8k16.row.col.f32.f16.f16.f32 "
        "{%0,%1,%2,%3}, {%4,%5,%6,%7}, {%8,%9}, {%0,%1,%2,%3};"
        : "+f"(d[0]), "+f"(d[1]), "+f"(d[2]), "+f"(d[3])
        : "r"(a[0]), "r"(a[1]), "r"(a[2]), "r"(a[3]), "r"(b[0]), "r"(b[1]));
}
__device__ __forceinline__ float tanh_fast(float x) {
    float y;
    asm("tanh.approx.f32 %0, %1;" : "=f"(y) : "f"(x));
    return y;
}
__device__ __forceinline__ float sigmoid_fast(float x) {
    return fmaf(0.5f, tanh_fast(0.5f * x), 0.5f);
}
__device__ __forceinline__ uint32_t pack_h2(float a, float b) {
    __half2 h = __floats2half2_rn(a, b);
    return *reinterpret_cast<uint32_t*>(&h);
}

__device__ __forceinline__ void grid_barrier() {
    __syncthreads();
    if (threadIdx.x == 0) {
        __threadfence();                       // release my writes
        unsigned int gen = g_bar_gen;          // read BEFORE arriving
        if (atomicAdd(&g_bar_count, 1u) == (unsigned)(NCTA - 1)) {
            g_bar_count = 0;
            __threadfence();                   // count reset before release
            g_bar_gen = gen + 1;
        } else {
            while (g_bar_gen == gen) { __nanosleep(32); }
            __threadfence();                   // acquire
        }
    }
    __syncthreads();
}

// ---------------- prep kernels ----------------
// Permuted z-col p: nt=p>>7, loc=p&127; wn=loc>>5, g=(loc>>3)&3, ul=loc&7;
// unit u = nt*32 + wn*8 + ul; original col oc = g*256 + u.
// ar=0: W = Wh ; ar=1: W = Wh + Wd@Wx (feedback folded).
__global__ void prep_b2(const float* __restrict__ Wh,
                        const float* __restrict__ Wd,
                        const float* __restrict__ Wx,
                        int ar, uint2* __restrict__ dst) {
    int idx = blockIdx.x * 256 + threadIdx.x;   // 65536 = 128 nt8 x 16 kc x 32
    int lane = idx & 31;
    int kc   = (idx >> 5) & 15;
    int ntile = idx >> 9;
    int q = lane >> 2, s = lane & 3;
    int p = ntile * 8 + q;                      // permuted z-col (n of frag)
    int nt = p >> 7, loc = p & 127;
    int wn = loc >> 5, g = (loc >> 3) & 3, ul = loc & 7;
    int oc = g * 256 + nt * 32 + wn * 8 + ul;   // original z column
    int k0 = kc * 16 + 2 * s;
    float v[4];
    const int kk[4] = {k0, k0 + 1, k0 + 8, k0 + 9};
    #pragma unroll
    for (int j = 0; j < 4; j++) {
        float w = Wh[kk[j] * Z4 + oc];
        if (ar) {
            #pragma unroll
            for (int f = 0; f < FDIM; f++)
                w = fmaf(Wd[kk[j] * FDIM + f], Wx[f * Z4 + oc], w);
        }
        v[j] = w;
    }
    uint2 r;
    r.x = pack_h2(v[0], v[1]);  // b0
    r.y = pack_h2(v[2], v[3]);  // b1
    dst[idx] = r;
}

__global__ void prep_wxb(const float* __restrict__ Wx,
                         const float* __restrict__ b,
                         const float* __restrict__ bd) {
    int p = threadIdx.x;                        // 0..1023
    int nt = p >> 7, loc = p & 127;
    int wn = loc >> 5, g = (loc >> 3) & 3, ul = loc & 7;
    int oc = g * 256 + nt * 32 + wn * 8 + ul;
    float bb = b[oc];
    g_bp[p] = bb;
    float ba = bb;
    #pragma unroll
    for (int f = 0; f < FDIM; f++) {
        g_wxp[f * Z4 + p] = Wx[f * Z4 + oc];
        ba = fmaf(bd[f], Wx[f * Z4 + oc], ba);
    }
    g_bpar[p] = ba;
}

// ---------------- persistent all-steps kernel ----------------
__global__ void __launch_bounds__(THREADS, 2)
lstm_persist(const float* __restrict__ x)
{
    __shared__ float wx_s[4 * 128];
    __shared__ float bpw_s[128];
    __shared__ float bpa_s[128];

    const int tid  = threadIdx.x;
    const int lane = tid & 31;
    const int wid  = tid >> 5;
    const int wm   = wid & 1;        // m-warp: rows wm*32..+32 (of 64)
    const int wn   = wid >> 1;       // n-warp: permuted cols wn*32..+32
    const int ct   = blockIdx.x;     // 0..255
    const int nt   = ct >> 5;        // 0..7 (fixed per CTA -> B reuse)
    const int rt0  = ct & 31;        // tiles rt = rt0 + 32*j, j=0..7

    for (int i = tid; i < 4 * 128; i += THREADS) {
        int f = i >> 7, j = i & 127;
        wx_s[i] = g_wxp[f * Z4 + nt * 128 + j];
    }
    if (tid < 128) {
        bpw_s[tid] = g_bp[nt * 128 + tid];
        bpa_s[tid] = g_bpar[nt * 128 + tid];
    }
    __syncthreads();

    const int q  = lane >> 2;
    const int s4 = lane & 3;
    const int kcs = nt * 2 + (wn >> 1);     // kchunk of this warp's units
    const int slotbase = (wn & 1) * 2;      // a0a1 (k<8) or a2a3 (k>=8)

    for (int t = 0; t < NSTEPS; t++) {
        const int warm = (t < SEQ_T);
        const uint2* __restrict__ b2 = warm ? g_b2w : g_b2ar;
        const float* bias = warm ? bpw_s : bpa_s;
        const uint4* __restrict__ a_in = g_a4h + ((t + 1) & 1) * BUFQ;
        uint4* __restrict__ a_out = g_a4h + (t & 1) * BUFQ;
        uint32_t* ah32 = reinterpret_cast<uint32_t*>(a_out);
        float* h_slot = nullptr;
        if (t == SEQ_T - 1)      h_slot = g_hall;
        else if (t >= SEQ_T)     h_slot = g_hall + (long)(t - SEQ_T + 1) * HSLOT;
        const float* xt = x + t * FDIM;

        for (int j = 0; j < 8; j++) {
            const int rt = rt0 + 32 * j;

            // accumulators d[mi][gate][frag]
            float d[2][4][4];
            #pragma unroll
            for (int mi = 0; mi < 2; mi++)
                #pragma unroll
                for (int g = 0; g < 4; g++)
                    #pragma unroll
                    for (int r = 0; r < 4; r++)
                        d[mi][g][r] = 0.0f;

            if (t > 0) {
                const int aBase = ((rt * 4 + wm * 2) * 16) * 32 + lane;
                const int bBase = ((nt * 16 + wn * 4) * 16) * 32 + lane;

                uint4 Ah[2][2];
                uint2 Bq[2][4];
                #pragma unroll
                for (int mi = 0; mi < 2; mi++)
                    Ah[0][mi] = __ldcg(&a_in[aBase + mi * 512]);
                #pragma unroll
                for (int g = 0; g < 4; g++)
                    Bq[0][g] = b2[bBase + g * 512];

                #pragma unroll
                for (int kc = 0; kc < NKC; kc++) {
                    const int cur = kc & 1, nx = cur ^ 1;
                    if (kc < NKC - 1) {
                        const int ko = (kc + 1) * 32;
                        #pragma unroll
                        for (int mi = 0; mi < 2; mi++)
                            Ah[nx][mi] = __ldcg(&a_in[aBase + mi * 512 + ko]);
                        #pragma unroll
                        for (int g = 0; g < 4; g++)
                            Bq[nx][g] = b2[bBase + g * 512 + ko];
                    }
                    #pragma unroll
                    for (int mi = 0; mi < 2; mi++) {
                        const uint32_t* ah =
                            reinterpret_cast<const uint32_t*>(&Ah[cur][mi]);
                        #pragma unroll
                        for (int g = 0; g < 4; g++) {
                            const uint32_t bh[2] = {Bq[cur][g].x, Bq[cur][g].y};
                            mma16816(d[mi][g], ah, bh);
                        }
                    }
                }
            }

            // ---- epilogue: z -> gates -> c,h; A-frag (+ fp32 h) ----
            #pragma unroll
            for (int mi = 0; mi < 2; mi++) {
                float hn[2][2];                      // [rh][par]
                #pragma unroll
                for (int rh = 0; rh < 2; rh++) {
                    const int row = rt * 64 + wm * 32 + mi * 16 + q + rh * 8;
                    float4 xv = make_float4(0.f, 0.f, 0.f, 0.f);
                    if (warm)
                        xv = *reinterpret_cast<const float4*>(
                            &xt[(long)row * (SEQ_T * FDIM)]);
                    const int ci = row * NU + nt * 32 + wn * 8 + s4 * 2;
                    float2 cold = (t == 0) ? make_float2(0.f, 0.f)
                        : *reinterpret_cast<const float2*>(&g_c[ci]);
                    const float coldv[2] = {cold.x, cold.y};
                    float cn2[2], hn2[2];
                    #pragma unroll
                    for (int par = 0; par < 2; par++) {
                        float z[4];
                        #pragma unroll
                        for (int g = 0; g < 4; g++) {
                            const int nl = wn * 32 + g * 8 + s4 * 2 + par;
                            float zz = bias[nl] + d[mi][g][rh * 2 + par];
                            if (warm) {
                                zz = fmaf(xv.x, wx_s[nl],       zz);
                                zz = fmaf(xv.y, wx_s[128 + nl], zz);
                                zz = fmaf(xv.z, wx_s[256 + nl], zz);
                                zz = fmaf(xv.w, wx_s[384 + nl], zz);
                            }
                            z[g] = zz;
                        }
                        const float ig = sigmoid_fast(z[0]);
                        const float fg = sigmoid_fast(z[1]);
                        const float gg = tanh_fast(z[2]);
                        const float og = sigmoid_fast(z[3]);
                        const float cn = fg * coldv[par] + ig * gg;
                        const float hv = og * tanh_fast(cn);
                        cn2[par] = cn;
                        hn2[par] = hv;
                        hn[rh][par] = hv;
                    }
                    *reinterpret_cast<float2*>(&g_c[ci]) =
                        make_float2(cn2[0], cn2[1]);
                    if (h_slot)
                        *reinterpret_cast<float2*>(&h_slot[ci]) =
                            make_float2(hn2[0], hn2[1]);
                }
                // A-fragment store (identity map)
                const int m16blk = rt * 4 + wm * 2 + mi;
                const int fb = ((m16blk * 16 + kcs) * 32 + lane) * 4 + slotbase;
                uint2 fh;
                fh.x = pack_h2(hn[0][0], hn[0][1]);
                fh.y = pack_h2(hn[1][0], hn[1][1]);
                *reinterpret_cast<uint2*>(&ah32[fb]) = fh;
            }
        }

        if (t < NSTEPS - 1) grid_barrier();
    }
}

// All 24 predictions in one launch: out[row, s, :] = hall[s, row, :]@Wd + bd
__global__ void pred_all(const float* __restrict__ hall,
                         const float* __restrict__ Wd,
                         const float* __restrict__ bd,
                         float* __restrict__ out)
{
    const int gwarp = (blockIdx.x * blockDim.x + threadIdx.x) >> 5;
    const int lane  = threadIdx.x & 31;
    if (gwarp >= NOUT * BATCH) return;
    const int s   = gwarp >> 14;          // / BATCH
    const int row = gwarp & (BATCH - 1);

    const float* hrow = hall + ((long)s * BATCH + row) * NU;
    float a0 = 0.f, a1 = 0.f, a2 = 0.f, a3 = 0.f;
    #pragma unroll
    for (int k = lane; k < NU; k += 32) {
        float hv = hrow[k];
        float4 wv = *reinterpret_cast<const float4*>(&Wd[k * 4]);
        a0 = fmaf(hv, wv.x, a0);
        a1 = fmaf(hv, wv.y, a1);
        a2 = fmaf(hv, wv.z, a2);
        a3 = fmaf(hv, wv.w, a3);
    }
    #pragma unroll
    for (int off = 16; off > 0; off >>= 1) {
        a0 += __shfl_down_sync(0xffffffffu, a0, off);
        a1 += __shfl_down_sync(0xffffffffu, a1, off);
        a2 += __shfl_down_sync(0xffffffffu, a2, off);
        a3 += __shfl_down_sync(0xffffffffu, a3, off);
    }
    if (lane == 0) {
        float4 r = make_float4(a0 + bd[0], a1 + bd[1], a2 + bd[2], a3 + bd[3]);
        *reinterpret_cast<float4*>(&out[((long)row * NOUT + s) * FDIM]) = r;
    }
}

extern "C" void kernel_launch(void* const* d_in, const int* in_sizes, int n_in,
                              void* d_out, int out_size)
{
    const float* x  = (const float*)d_in[0];
    const float* Wx = (const float*)d_in[1];
    const float* Wh = (const float*)d_in[2];
    const float* b  = (const float*)d_in[3];
    const float* Wd = (const float*)d_in[4];
    const float* bd = (const float*)d_in[5];
    float* out = (float*)d_out;

    uint2 *b2w = nullptr, *b2ar = nullptr;
    float* hall = nullptr;
    cudaGetSymbolAddress((void**)&b2w, g_b2w);
    cudaGetSymbolAddress((void**)&b2ar, g_b2ar);
    cudaGetSymbolAddress((void**)&hall, g_hall);

    // weight prep (re-run every replay -> deterministic)
    prep_b2<<<256, 256>>>(Wh, Wd, Wx, 0, b2w);
    prep_b2<<<256, 256>>>(Wh, Wd, Wx, 1, b2ar);
    prep_wxb<<<1, 1024>>>(Wx, b, bd);

    // all 71 recurrent steps in one persistent kernel
    lstm_persist<<<NCTA, THREADS>>>(x);

    // all predictions in one shot
    const int pblocks = (NOUT * BATCH * 32) / 256;
    pred_all<<<pblocks, 256>>>(hall, Wd, bd, out);
}

// round 14
// speedup vs baseline: 7.0773x; 1.1333x over previous
#include <cuda_runtime.h>
#include <cuda_fp16.h>
#include <cstdint>

// ---------------------------------------------------------------------------
// FeedBack LSTM via mma.sync fp16 (baseline PTX; sm_103 target, no 'a' feats).
// R14: persistent kernel, c state in SMEM (thread-private slots — each
// (row,unit) is owned by one thread for all 71 steps, so c never touches
// gmem), 296 CTAs = exactly 2/SM (balanced; grid barrier syncs to max).
// Single-term fp16 GEMM (R12 math): z = Ah·Bh, folded AR weights
// (Wh' = Wh + Wd@Wx), MUFU activations, one pred_all at the end.
// B=16384, T=48, F=4, UNITS=256 (z width 1024), OUT_STEPS=24.
// ---------------------------------------------------------------------------

namespace {
constexpr int BATCH = 16384;
constexpr int SEQ_T = 48;
constexpr int FDIM  = 4;
constexpr int NU    = 256;
constexpr int NOUT  = 24;
constexpr int Z4    = 1024;

constexpr int THREADS = 256;   // 8 warps: 2 m-warps x 4 n-warps (warp 32x32)
constexpr int NM16 = BATCH / 16;        // 1024 m16 blocks
constexpr int NKC  = NU / 16;           // 16 k16 chunks
constexpr int NT8  = Z4 / 8;            // 128 n8 tiles
constexpr int NCTA = 296;               // exactly 2 CTAs per SM (148 SMs)
constexpr int CPN  = NCTA / 8;          // 37 CTAs per nt
constexpr int NTILE_MAX = 7;            // ceil(256/37)
constexpr int NSTEPS = SEQ_T + NOUT - 1;  // 71
constexpr long BUFQ = (long)NM16 * NKC * 32;
constexpr long HSLOT = (long)BATCH * NU;
// dynamic smem: c[NTILE_MAX][8][256] floats
constexpr int CSMEM_BYTES = NTILE_MAX * 8 * 256 * 4;   // 57344
}

// ---------------- device state (allocation-free) ----------------
// A fragments (fp16 hi): [buf][m16blk(1024)][kchunk(16)][lane(32)] : uint4
__device__ __align__(16) uint4 g_a4h[2 * NM16 * NKC * 32];
// B fragments (fp16): [ntile(128)][kchunk(16)][lane(32)] : uint2 = b0,b1
__device__ __align__(16) uint2 g_b2w[NT8 * NKC * 32];    // warmup: Wh
__device__ __align__(16) uint2 g_b2ar[NT8 * NKC * 32];   // AR: Wh + Wd@Wx
// permuted Wx / biases (fp32)
__device__ float g_wxp[FDIM * Z4];
__device__ float g_bp[Z4];       // permuted b
__device__ float g_bpar[Z4];     // permuted b + bd@Wx
// per-output-step h slots (slot 0 = warmup final; slot s = AR step s)
__device__ float g_hall[NOUT * BATCH * NU];
// grid barrier state (gen monotonic across replays; count self-resets)
__device__ volatile unsigned int g_bar_gen;
__device__ unsigned int g_bar_count;

// ---------------- helpers ----------------
__device__ __forceinline__ void mma16816(float* d, const uint32_t* a,
                                         const uint32_t* b) {
    asm volatile(
        "mma.sync.aligned.m16n8k16.row.col.f32.f16.f16.f32 "
        "{%0,%1,%2,%3}, {%4,%5,%6,%7}, {%8,%9}, {%0,%1,%2,%3};"
        : "+f"(d[0]), "+f"(d[1]), "+f"(d[2]), "+f"(d[3])
        : "r"(a[0]), "r"(a[1]), "r"(a[2]), "r"(a[3]), "r"(b[0]), "r"(b[1]));
}
__device__ __forceinline__ float tanh_fast(float x) {
    float y;
    asm("tanh.approx.f32 %0, %1;" : "=f"(y) : "f"(x));
    return y;
}
__device__ __forceinline__ float sigmoid_fast(float x) {
    return fmaf(0.5f, tanh_fast(0.5f * x), 0.5f);
}
__device__ __forceinline__ uint32_t pack_h2(float a, float b) {
    __half2 h = __floats2half2_rn(a, b);
    return *reinterpret_cast<uint32_t*>(&h);
}

__device__ __forceinline__ void grid_barrier() {
    __syncthreads();
    if (threadIdx.x == 0) {
        __threadfence();                       // release my writes
        unsigned int gen = g_bar_gen;          // read BEFORE arriving
        if (atomicAdd(&g_bar_count, 1u) == (unsigned)(NCTA - 1)) {
            g_bar_count = 0;
            __threadfence();                   // count reset before release
            g_bar_gen = gen + 1;
        } else {
            while (g_bar_gen == gen) { __nanosleep(32); }
            __threadfence();                   // acquire
        }
    }
    __syncthreads();
}

// ---------------- prep kernels ----------------
// Permuted z-col p: nt=p>>7, loc=p&127; wn=loc>>5, g=(loc>>3)&3, ul=loc&7;
// unit u = nt*32 + wn*8 + ul; original col oc = g*256 + u.
// ar=0: W = Wh ; ar=1: W = Wh + Wd@Wx (feedback folded).
__global__ void prep_b2(const float* __restrict__ Wh,
                        const float* __restrict__ Wd,
                        const float* __restrict__ Wx,
                        int ar, uint2* __restrict__ dst) {
    int idx = blockIdx.x * 256 + threadIdx.x;   // 65536 = 128 nt8 x 16 kc x 32
    int lane = idx & 31;
    int kc   = (idx >> 5) & 15;
    int ntile = idx >> 9;
    int q = lane >> 2, s = lane & 3;
    int p = ntile * 8 + q;                      // permuted z-col (n of frag)
    int nt = p >> 7, loc = p & 127;
    int wn = loc >> 5, g = (loc >> 3) & 3, ul = loc & 7;
    int oc = g * 256 + nt * 32 + wn * 8 + ul;   // original z column
    int k0 = kc * 16 + 2 * s;
    float v[4];
    const int kk[4] = {k0, k0 + 1, k0 + 8, k0 + 9};
    #pragma unroll
    for (int j = 0; j < 4; j++) {
        float w = Wh[kk[j] * Z4 + oc];
        if (ar) {
            #pragma unroll
            for (int f = 0; f < FDIM; f++)
                w = fmaf(Wd[kk[j] * FDIM + f], Wx[f * Z4 + oc], w);
        }
        v[j] = w;
    }
    uint2 r;
    r.x = pack_h2(v[0], v[1]);  // b0
    r.y = pack_h2(v[2], v[3]);  // b1
    dst[idx] = r;
}

__global__ void prep_wxb(const float* __restrict__ Wx,
                         const float* __restrict__ b,
                         const float* __restrict__ bd) {
    int p = threadIdx.x;                        // 0..1023
    int nt = p >> 7, loc = p & 127;
    int wn = loc >> 5, g = (loc >> 3) & 3, ul = loc & 7;
    int oc = g * 256 + nt * 32 + wn * 8 + ul;
    float bb = b[oc];
    g_bp[p] = bb;
    float ba = bb;
    #pragma unroll
    for (int f = 0; f < FDIM; f++) {
        g_wxp[f * Z4 + p] = Wx[f * Z4 + oc];
        ba = fmaf(bd[f], Wx[f * Z4 + oc], ba);
    }
    g_bpar[p] = ba;
}

// ---------------- persistent all-steps kernel ----------------
__global__ void __launch_bounds__(THREADS, 2)
lstm_persist(const float* __restrict__ x)
{
    extern __shared__ float c_s[];            // [NTILE_MAX][8][256]
    __shared__ float wx_s[4 * 128];
    __shared__ float bpw_s[128];
    __shared__ float bpa_s[128];

    const int tid  = threadIdx.x;
    const int lane = tid & 31;
    const int wid  = tid >> 5;
    const int wm   = wid & 1;        // m-warp: rows wm*32..+32 (of 64)
    const int wn   = wid >> 1;       // n-warp: permuted cols wn*32..+32
    const int ct   = blockIdx.x;     // 0..295
    const int nt   = ct & 7;         // fixed per CTA -> B reuse
    const int ci   = ct >> 3;        // 0..36; tiles rt = ci + 37*j

    for (int i = tid; i < 4 * 128; i += THREADS) {
        int f = i >> 7, j = i & 127;
        wx_s[i] = g_wxp[f * Z4 + nt * 128 + j];
    }
    if (tid < 128) {
        bpw_s[tid] = g_bp[nt * 128 + tid];
        bpa_s[tid] = g_bpar[nt * 128 + tid];
    }
    __syncthreads();

    const int q  = lane >> 2;
    const int s4 = lane & 3;
    const int kcs = nt * 2 + (wn >> 1);     // kchunk of this warp's units
    const int slotbase = (wn & 1) * 2;      // a0a1 (k<8) or a2a3 (k>=8)

    for (int t = 0; t < NSTEPS; t++) {
        const int warm = (t < SEQ_T);
        const uint2* __restrict__ b2 = warm ? g_b2w : g_b2ar;
        const float* bias = warm ? bpw_s : bpa_s;
        const uint4* __restrict__ a_in = g_a4h + ((t + 1) & 1) * BUFQ;
        uint4* __restrict__ a_out = g_a4h + (t & 1) * BUFQ;
        uint32_t* ah32 = reinterpret_cast<uint32_t*>(a_out);
        float* h_slot = nullptr;
        if (t == SEQ_T - 1)      h_slot = g_hall;
        else if (t >= SEQ_T)     h_slot = g_hall + (long)(t - SEQ_T + 1) * HSLOT;
        const float* xt = x + t * FDIM;

        int jt = 0;
        for (int rt = ci; rt < 256; rt += CPN, jt++) {
            // accumulators d[mi][gate][frag]
            float d[2][4][4];
            #pragma unroll
            for (int mi = 0; mi < 2; mi++)
                #pragma unroll
                for (int g = 0; g < 4; g++)
                    #pragma unroll
                    for (int r = 0; r < 4; r++)
                        d[mi][g][r] = 0.0f;

            if (t > 0) {
                const int aBase = ((rt * 4 + wm * 2) * 16) * 32 + lane;
                const int bBase = ((nt * 16 + wn * 4) * 16) * 32 + lane;

                uint4 Ah[2][2];
                uint2 Bq[2][4];
                #pragma unroll
                for (int mi = 0; mi < 2; mi++)
                    Ah[0][mi] = __ldcg(&a_in[aBase + mi * 512]);
                #pragma unroll
                for (int g = 0; g < 4; g++)
                    Bq[0][g] = b2[bBase + g * 512];

                #pragma unroll
                for (int kc = 0; kc < NKC; kc++) {
                    const int cur = kc & 1, nx = cur ^ 1;
                    if (kc < NKC - 1) {
                        const int ko = (kc + 1) * 32;
                        #pragma unroll
                        for (int mi = 0; mi < 2; mi++)
                            Ah[nx][mi] = __ldcg(&a_in[aBase + mi * 512 + ko]);
                        #pragma unroll
                        for (int g = 0; g < 4; g++)
                            Bq[nx][g] = b2[bBase + g * 512 + ko];
                    }
                    #pragma unroll
                    for (int mi = 0; mi < 2; mi++) {
                        const uint32_t* ah =
                            reinterpret_cast<const uint32_t*>(&Ah[cur][mi]);
                        #pragma unroll
                        for (int g = 0; g < 4; g++) {
                            const uint32_t bh[2] = {Bq[cur][g].x, Bq[cur][g].y};
                            mma16816(d[mi][g], ah, bh);
                        }
                    }
                }
            }

            // ---- epilogue: z -> gates -> c,h; A-frag (+ fp32 h) ----
            float* cslot = c_s + (jt * 8) * 256 + tid;   // [val][256] stride
            #pragma unroll
            for (int mi = 0; mi < 2; mi++) {
                float hn[2][2];                      // [rh][par]
                #pragma unroll
                for (int rh = 0; rh < 2; rh++) {
                    const int row = rt * 64 + wm * 32 + mi * 16 + q + rh * 8;
                    float4 xv = make_float4(0.f, 0.f, 0.f, 0.f);
                    if (warm)
                        xv = *reinterpret_cast<const float4*>(
                            &xt[(long)row * (SEQ_T * FDIM)]);
                    float hn2[2];
                    #pragma unroll
                    for (int par = 0; par < 2; par++) {
                        const int vofs = (mi * 4 + rh * 2 + par) * 256;
                        const float cold = (t == 0) ? 0.0f : cslot[vofs];
                        float z[4];
                        #pragma unroll
                        for (int g = 0; g < 4; g++) {
                            const int nl = wn * 32 + g * 8 + s4 * 2 + par;
                            float zz = bias[nl] + d[mi][g][rh * 2 + par];
                            if (warm) {
                                zz = fmaf(xv.x, wx_s[nl],       zz);
                                zz = fmaf(xv.y, wx_s[128 + nl], zz);
                                zz = fmaf(xv.z, wx_s[256 + nl], zz);
                                zz = fmaf(xv.w, wx_s[384 + nl], zz);
                            }
                            z[g] = zz;
                        }
                        const float ig = sigmoid_fast(z[0]);
                        const float fg = sigmoid_fast(z[1]);
                        const float gg = tanh_fast(z[2]);
                        const float og = sigmoid_fast(z[3]);
                        const float cn = fg * cold + ig * gg;
                        const float hv = og * tanh_fast(cn);
                        cslot[vofs] = cn;
                        hn2[par] = hv;
                        hn[rh][par] = hv;
                    }
                    if (h_slot) {
                        const int hi = row * NU + nt * 32 + wn * 8 + s4 * 2;
                        *reinterpret_cast<float2*>(&h_slot[hi]) =
                            make_float2(hn2[0], hn2[1]);
                    }
                }
                // A-fragment store (identity map)
                const int m16blk = rt * 4 + wm * 2 + mi;
                const int fb = ((m16blk * 16 + kcs) * 32 + lane) * 4 + slotbase;
                uint2 fh;
                fh.x = pack_h2(hn[0][0], hn[0][1]);
                fh.y = pack_h2(hn[1][0], hn[1][1]);
                *reinterpret_cast<uint2*>(&ah32[fb]) = fh;
            }
        }

        if (t < NSTEPS - 1) grid_barrier();
    }
}

// All 24 predictions in one launch: out[row, s, :] = hall[s, row, :]@Wd + bd
__global__ void pred_all(const float* __restrict__ hall,
                         const float* __restrict__ Wd,
                         const float* __restrict__ bd,
                         float* __restrict__ out)
{
    const int gwarp = (blockIdx.x * blockDim.x + threadIdx.x) >> 5;
    const int lane  = threadIdx.x & 31;
    if (gwarp >= NOUT * BATCH) return;
    const int s   = gwarp >> 14;          // / BATCH
    const int row = gwarp & (BATCH - 1);

    const float* hrow = hall + ((long)s * BATCH + row) * NU;
    float a0 = 0.f, a1 = 0.f, a2 = 0.f, a3 = 0.f;
    #pragma unroll
    for (int k = lane; k < NU; k += 32) {
        float hv = hrow[k];
        float4 wv = *reinterpret_cast<const float4*>(&Wd[k * 4]);
        a0 = fmaf(hv, wv.x, a0);
        a1 = fmaf(hv, wv.y, a1);
        a2 = fmaf(hv, wv.z, a2);
        a3 = fmaf(hv, wv.w, a3);
    }
    #pragma unroll
    for (int off = 16; off > 0; off >>= 1) {
        a0 += __shfl_down_sync(0xffffffffu, a0, off);
        a1 += __shfl_down_sync(0xffffffffu, a1, off);
        a2 += __shfl_down_sync(0xffffffffu, a2, off);
        a3 += __shfl_down_sync(0xffffffffu, a3, off);
    }
    if (lane == 0) {
        float4 r = make_float4(a0 + bd[0], a1 + bd[1], a2 + bd[2], a3 + bd[3]);
        *reinterpret_cast<float4*>(&out[((long)row * NOUT + s) * FDIM]) = r;
    }
}

extern "C" void kernel_launch(void* const* d_in, const int* in_sizes, int n_in,
                              void* d_out, int out_size)
{
    const float* x  = (const float*)d_in[0];
    const float* Wx = (const float*)d_in[1];
    const float* Wh = (const float*)d_in[2];
    const float* b  = (const float*)d_in[3];
    const float* Wd = (const float*)d_in[4];
    const float* bd = (const float*)d_in[5];
    float* out = (float*)d_out;

    uint2 *b2w = nullptr, *b2ar = nullptr;
    float* hall = nullptr;
    cudaGetSymbolAddress((void**)&b2w, g_b2w);
    cudaGetSymbolAddress((void**)&b2ar, g_b2ar);
    cudaGetSymbolAddress((void**)&hall, g_hall);

    cudaFuncSetAttribute(lstm_persist,
                         cudaFuncAttributeMaxDynamicSharedMemorySize,
                         CSMEM_BYTES);

    // weight prep (re-run every replay -> deterministic)
    prep_b2<<<256, 256>>>(Wh, Wd, Wx, 0, b2w);
    prep_b2<<<256, 256>>>(Wh, Wd, Wx, 1, b2ar);
    prep_wxb<<<1, 1024>>>(Wx, b, bd);

    // all 71 recurrent steps in one persistent kernel
    lstm_persist<<<NCTA, THREADS, CSMEM_BYTES>>>(x);

    // all predictions in one shot
    const int pblocks = (NOUT * BATCH * 32) / 256;
    pred_all<<<pblocks, 256>>>(hall, Wd, bd, out);
}

// round 15
// speedup vs baseline: 7.3737x; 1.0419x over previous
#include <cuda_runtime.h>
#include <cuda_fp16.h>
#include <cstdint>

// ---------------------------------------------------------------------------
// FeedBack LSTM via mma.sync fp16 (baseline PTX; sm_103 target, no 'a' feats).
// R15: the recurrence factorizes across row-groups -> the 296-CTA global
// barrier is replaced by 37 INDEPENDENT 8-CTA group barriers (CTAs sharing
// ci exchange A-frags; groups never interact). Persistent kernel, c in SMEM,
// single-term fp16 GEMM (z = Ah·Bh), folded AR weights, MUFU activations,
// one pred_all at the end.
// B=16384, T=48, F=4, UNITS=256 (z width 1024), OUT_STEPS=24.
// ---------------------------------------------------------------------------

namespace {
constexpr int BATCH = 16384;
constexpr int SEQ_T = 48;
constexpr int FDIM  = 4;
constexpr int NU    = 256;
constexpr int NOUT  = 24;
constexpr int Z4    = 1024;

constexpr int THREADS = 256;   // 8 warps: 2 m-warps x 4 n-warps (warp 32x32)
constexpr int NM16 = BATCH / 16;        // 1024 m16 blocks
constexpr int NKC  = NU / 16;           // 16 k16 chunks
constexpr int NT8  = Z4 / 8;            // 128 n8 tiles
constexpr int NCTA = 296;               // exactly 2 CTAs per SM (148 SMs)
constexpr int NGRP = 37;                // row groups (8 CTAs each)
constexpr int NTILE_MAX = 7;            // ceil(256/37)
constexpr int NSTEPS = SEQ_T + NOUT - 1;  // 71
constexpr long BUFQ = (long)NM16 * NKC * 32;
constexpr long HSLOT = (long)BATCH * NU;
// dynamic smem: c[NTILE_MAX][8][256] floats
constexpr int CSMEM_BYTES = NTILE_MAX * 8 * 256 * 4;   // 57344
constexpr int BARSTRIDE = 32;           // ints; 128B padding per group
}

// ---------------- device state (allocation-free) ----------------
// A fragments (fp16 hi): [buf][m16blk(1024)][kchunk(16)][lane(32)] : uint4
__device__ __align__(16) uint4 g_a4h[2 * NM16 * NKC * 32];
// B fragments (fp16): [ntile(128)][kchunk(16)][lane(32)] : uint2 = b0,b1
__device__ __align__(16) uint2 g_b2w[NT8 * NKC * 32];    // warmup: Wh
__device__ __align__(16) uint2 g_b2ar[NT8 * NKC * 32];   // AR: Wh + Wd@Wx
// permuted Wx / biases (fp32)
__device__ float g_wxp[FDIM * Z4];
__device__ float g_bp[Z4];       // permuted b
__device__ float g_bpar[Z4];     // permuted b + bd@Wx
// per-output-step h slots (slot 0 = warmup final; slot s = AR step s)
__device__ float g_hall[NOUT * BATCH * NU];
// per-group barrier state (gen monotonic across replays; count self-resets)
__device__ volatile unsigned int g_bar_gen[NGRP * BARSTRIDE];
__device__ unsigned int g_bar_count[NGRP * BARSTRIDE];

// ---------------- helpers ----------------
__device__ __forceinline__ void mma16816(float* d, const uint32_t* a,
                                         const uint32_t* b) {
    asm volatile(
        "mma.sync.aligned.m16n8k16.row.col.f32.f16.f16.f32 "
        "{%0,%1,%2,%3}, {%4,%5,%6,%7}, {%8,%9}, {%0,%1,%2,%3};"
        : "+f"(d[0]), "+f"(d[1]), "+f"(d[2]), "+f"(d[3])
        : "r"(a[0]), "r"(a[1]), "r"(a[2]), "r"(a[3]), "r"(b[0]), "r"(b[1]));
}
__device__ __forceinline__ float tanh_fast(float x) {
    float y;
    asm("tanh.approx.f32 %0, %1;" : "=f"(y) : "f"(x));
    return y;
}
__device__ __forceinline__ float sigmoid_fast(float x) {
    return fmaf(0.5f, tanh_fast(0.5f * x), 0.5f);
}
__device__ __forceinline__ uint32_t pack_h2(float a, float b) {
    __half2 h = __floats2half2_rn(a, b);
    return *reinterpret_cast<uint32_t*>(&h);
}

// 8-CTA group barrier (group = ci); padded counters, few waiters.
__device__ __forceinline__ void group_barrier(int gid) {
    __syncthreads();
    if (threadIdx.x == 0) {
        const int slot = gid * BARSTRIDE;
        __threadfence();                       // release my writes
        unsigned int gen = g_bar_gen[slot];    // read BEFORE arriving
        if (atomicAdd(&g_bar_count[slot], 1u) == 7u) {
            g_bar_count[slot] = 0;
            __threadfence();                   // count reset before release
            g_bar_gen[slot] = gen + 1;
        } else {
            while (g_bar_gen[slot] == gen) { __nanosleep(32); }
            __threadfence();                   // acquire
        }
    }
    __syncthreads();
}

// ---------------- prep kernels ----------------
// Permuted z-col p: nt=p>>7, loc=p&127; wn=loc>>5, g=(loc>>3)&3, ul=loc&7;
// unit u = nt*32 + wn*8 + ul; original col oc = g*256 + u.
// ar=0: W = Wh ; ar=1: W = Wh + Wd@Wx (feedback folded).
__global__ void prep_b2(const float* __restrict__ Wh,
                        const float* __restrict__ Wd,
                        const float* __restrict__ Wx,
                        int ar, uint2* __restrict__ dst) {
    int idx = blockIdx.x * 256 + threadIdx.x;   // 65536 = 128 nt8 x 16 kc x 32
    int lane = idx & 31;
    int kc   = (idx >> 5) & 15;
    int ntile = idx >> 9;
    int q = lane >> 2, s = lane & 3;
    int p = ntile * 8 + q;                      // permuted z-col (n of frag)
    int nt = p >> 7, loc = p & 127;
    int wn = loc >> 5, g = (loc >> 3) & 3, ul = loc & 7;
    int oc = g * 256 + nt * 32 + wn * 8 + ul;   // original z column
    int k0 = kc * 16 + 2 * s;
    float v[4];
    const int kk[4] = {k0, k0 + 1, k0 + 8, k0 + 9};
    #pragma unroll
    for (int j = 0; j < 4; j++) {
        float w = Wh[kk[j] * Z4 + oc];
        if (ar) {
            #pragma unroll
            for (int f = 0; f < FDIM; f++)
                w = fmaf(Wd[kk[j] * FDIM + f], Wx[f * Z4 + oc], w);
        }
        v[j] = w;
    }
    uint2 r;
    r.x = pack_h2(v[0], v[1]);  // b0
    r.y = pack_h2(v[2], v[3]);  // b1
    dst[idx] = r;
}

__global__ void prep_wxb(const float* __restrict__ Wx,
                         const float* __restrict__ b,
                         const float* __restrict__ bd) {
    int p = threadIdx.x;                        // 0..1023
    int nt = p >> 7, loc = p & 127;
    int wn = loc >> 5, g = (loc >> 3) & 3, ul = loc & 7;
    int oc = g * 256 + nt * 32 + wn * 8 + ul;
    float bb = b[oc];
    g_bp[p] = bb;
    float ba = bb;
    #pragma unroll
    for (int f = 0; f < FDIM; f++) {
        g_wxp[f * Z4 + p] = Wx[f * Z4 + oc];
        ba = fmaf(bd[f], Wx[f * Z4 + oc], ba);
    }
    g_bpar[p] = ba;
}

// ---------------- persistent all-steps kernel ----------------
__global__ void __launch_bounds__(THREADS, 2)
lstm_persist(const float* __restrict__ x)
{
    extern __shared__ float c_s[];            // [NTILE_MAX][8][256]
    __shared__ float wx_s[4 * 128];
    __shared__ float bpw_s[128];
    __shared__ float bpa_s[128];

    const int tid  = threadIdx.x;
    const int lane = tid & 31;
    const int wid  = tid >> 5;
    const int wm   = wid & 1;        // m-warp: rows wm*32..+32 (of 64)
    const int wn   = wid >> 1;       // n-warp: permuted cols wn*32..+32
    const int ct   = blockIdx.x;     // 0..295
    const int nt   = ct & 7;         // fixed per CTA -> B reuse
    const int ci   = ct >> 3;        // 0..36 = row group id; rt = ci + 37*j

    for (int i = tid; i < 4 * 128; i += THREADS) {
        int f = i >> 7, j = i & 127;
        wx_s[i] = g_wxp[f * Z4 + nt * 128 + j];
    }
    if (tid < 128) {
        bpw_s[tid] = g_bp[nt * 128 + tid];
        bpa_s[tid] = g_bpar[nt * 128 + tid];
    }
    __syncthreads();

    const int q  = lane >> 2;
    const int s4 = lane & 3;
    const int kcs = nt * 2 + (wn >> 1);     // kchunk of this warp's units
    const int slotbase = (wn & 1) * 2;      // a0a1 (k<8) or a2a3 (k>=8)

    for (int t = 0; t < NSTEPS; t++) {
        const int warm = (t < SEQ_T);
        const uint2* __restrict__ b2 = warm ? g_b2w : g_b2ar;
        const float* bias = warm ? bpw_s : bpa_s;
        const uint4* __restrict__ a_in = g_a4h + ((t + 1) & 1) * BUFQ;
        uint4* __restrict__ a_out = g_a4h + (t & 1) * BUFQ;
        uint32_t* ah32 = reinterpret_cast<uint32_t*>(a_out);
        float* h_slot = nullptr;
        if (t == SEQ_T - 1)      h_slot = g_hall;
        else if (t >= SEQ_T)     h_slot = g_hall + (long)(t - SEQ_T + 1) * HSLOT;
        const float* xt = x + t * FDIM;

        int jt = 0;
        for (int rt = ci; rt < 256; rt += NGRP, jt++) {
            // accumulators d[mi][gate][frag]
            float d[2][4][4];
            #pragma unroll
            for (int mi = 0; mi < 2; mi++)
                #pragma unroll
                for (int g = 0; g < 4; g++)
                    #pragma unroll
                    for (int r = 0; r < 4; r++)
                        d[mi][g][r] = 0.0f;

            if (t > 0) {
                const int aBase = ((rt * 4 + wm * 2) * 16) * 32 + lane;
                const int bBase = ((nt * 16 + wn * 4) * 16) * 32 + lane;

                uint4 Ah[2][2];
                uint2 Bq[2][4];
                #pragma unroll
                for (int mi = 0; mi < 2; mi++)
                    Ah[0][mi] = __ldcg(&a_in[aBase + mi * 512]);
                #pragma unroll
                for (int g = 0; g < 4; g++)
                    Bq[0][g] = b2[bBase + g * 512];

                #pragma unroll
                for (int kc = 0; kc < NKC; kc++) {
                    const int cur = kc & 1, nx = cur ^ 1;
                    if (kc < NKC - 1) {
                        const int ko = (kc + 1) * 32;
                        #pragma unroll
                        for (int mi = 0; mi < 2; mi++)
                            Ah[nx][mi] = __ldcg(&a_in[aBase + mi * 512 + ko]);
                        #pragma unroll
                        for (int g = 0; g < 4; g++)
                            Bq[nx][g] = b2[bBase + g * 512 + ko];
                    }
                    #pragma unroll
                    for (int mi = 0; mi < 2; mi++) {
                        const uint32_t* ah =
                            reinterpret_cast<const uint32_t*>(&Ah[cur][mi]);
                        #pragma unroll
                        for (int g = 0; g < 4; g++) {
                            const uint32_t bh[2] = {Bq[cur][g].x, Bq[cur][g].y};
                            mma16816(d[mi][g], ah, bh);
                        }
                    }
                }
            }

            // ---- epilogue: z -> gates -> c,h; A-frag (+ fp32 h) ----
            float* cslot = c_s + (jt * 8) * 256 + tid;   // [val][256] stride
            #pragma unroll
            for (int mi = 0; mi < 2; mi++) {
                float hn[2][2];                      // [rh][par]
                #pragma unroll
                for (int rh = 0; rh < 2; rh++) {
                    const int row = rt * 64 + wm * 32 + mi * 16 + q + rh * 8;
                    float4 xv = make_float4(0.f, 0.f, 0.f, 0.f);
                    if (warm)
                        xv = *reinterpret_cast<const float4*>(
                            &xt[(long)row * (SEQ_T * FDIM)]);
                    float hn2[2];
                    #pragma unroll
                    for (int par = 0; par < 2; par++) {
                        const int vofs = (mi * 4 + rh * 2 + par) * 256;
                        const float cold = (t == 0) ? 0.0f : cslot[vofs];
                        float z[4];
                        #pragma unroll
                        for (int g = 0; g < 4; g++) {
                            const int nl = wn * 32 + g * 8 + s4 * 2 + par;
                            float zz = bias[nl] + d[mi][g][rh * 2 + par];
                            if (warm) {
                                zz = fmaf(xv.x, wx_s[nl],       zz);
                                zz = fmaf(xv.y, wx_s[128 + nl], zz);
                                zz = fmaf(xv.z, wx_s[256 + nl], zz);
                                zz = fmaf(xv.w, wx_s[384 + nl], zz);
                            }
                            z[g] = zz;
                        }
                        const float ig = sigmoid_fast(z[0]);
                        const float fg = sigmoid_fast(z[1]);
                        const float gg = tanh_fast(z[2]);
                        const float og = sigmoid_fast(z[3]);
                        const float cn = fg * cold + ig * gg;
                        const float hv = og * tanh_fast(cn);
                        cslot[vofs] = cn;
                        hn2[par] = hv;
                        hn[rh][par] = hv;
                    }
                    if (h_slot) {
                        const int hi = row * NU + nt * 32 + wn * 8 + s4 * 2;
                        *reinterpret_cast<float2*>(&h_slot[hi]) =
                            make_float2(hn2[0], hn2[1]);
                    }
                }
                // A-fragment store (identity map)
                const int m16blk = rt * 4 + wm * 2 + mi;
                const int fb = ((m16blk * 16 + kcs) * 32 + lane) * 4 + slotbase;
                uint2 fh;
                fh.x = pack_h2(hn[0][0], hn[0][1]);
                fh.y = pack_h2(hn[1][0], hn[1][1]);
                *reinterpret_cast<uint2*>(&ah32[fb]) = fh;
            }
        }

        if (t < NSTEPS - 1) group_barrier(ci);
    }
}

// All 24 predictions in one launch: out[row, s, :] = hall[s, row, :]@Wd + bd
__global__ void pred_all(const float* __restrict__ hall,
                         const float* __restrict__ Wd,
                         const float* __restrict__ bd,
                         float* __restrict__ out)
{
    const int gwarp = (blockIdx.x * blockDim.x + threadIdx.x) >> 5;
    const int lane  = threadIdx.x & 31;
    if (gwarp >= NOUT * BATCH) return;
    const int s   = gwarp >> 14;          // / BATCH
    const int row = gwarp & (BATCH - 1);

    const float* hrow = hall + ((long)s * BATCH + row) * NU;
    float a0 = 0.f, a1 = 0.f, a2 = 0.f, a3 = 0.f;
    #pragma unroll
    for (int k = lane; k < NU; k += 32) {
        float hv = hrow[k];
        float4 wv = *reinterpret_cast<const float4*>(&Wd[k * 4]);
        a0 = fmaf(hv, wv.x, a0);
        a1 = fmaf(hv, wv.y, a1);
        a2 = fmaf(hv, wv.z, a2);
        a3 = fmaf(hv, wv.w, a3);
    }
    #pragma unroll
    for (int off = 16; off > 0; off >>= 1) {
        a0 += __shfl_down_sync(0xffffffffu, a0, off);
        a1 += __shfl_down_sync(0xffffffffu, a1, off);
        a2 += __shfl_down_sync(0xffffffffu, a2, off);
        a3 += __shfl_down_sync(0xffffffffu, a3, off);
    }
    if (lane == 0) {
        float4 r = make_float4(a0 + bd[0], a1 + bd[1], a2 + bd[2], a3 + bd[3]);
        *reinterpret_cast<float4*>(&out[((long)row * NOUT + s) * FDIM]) = r;
    }
}

extern "C" void kernel_launch(void* const* d_in, const int* in_sizes, int n_in,
                              void* d_out, int out_size)
{
    const float* x  = (const float*)d_in[0];
    const float* Wx = (const float*)d_in[1];
    const float* Wh = (const float*)d_in[2];
    const float* b  = (const float*)d_in[3];
    const float* Wd = (const float*)d_in[4];
    const float* bd = (const float*)d_in[5];
    float* out = (float*)d_out;

    uint2 *b2w = nullptr, *b2ar = nullptr;
    float* hall = nullptr;
    cudaGetSymbolAddress((void**)&b2w, g_b2w);
    cudaGetSymbolAddress((void**)&b2ar, g_b2ar);
    cudaGetSymbolAddress((void**)&hall, g_hall);

    cudaFuncSetAttribute(lstm_persist,
                         cudaFuncAttributeMaxDynamicSharedMemorySize,
                         CSMEM_BYTES);

    // weight prep (re-run every replay -> deterministic)
    prep_b2<<<256, 256>>>(Wh, Wd, Wx, 0, b2w);
    prep_b2<<<256, 256>>>(Wh, Wd, Wx, 1, b2ar);
    prep_wxb<<<1, 1024>>>(Wx, b, bd);

    // all 71 recurrent steps in one persistent kernel
    lstm_persist<<<NCTA, THREADS, CSMEM_BYTES>>>(x);

    // all predictions in one shot
    const int pblocks = (NOUT * BATCH * 32) / 256;
    pred_all<<<pblocks, 256>>>(hall, Wd, bd, out);
}